// round 4
// baseline (speedup 1.0000x reference)
#include <cuda_runtime.h>
#include <math.h>

#define NN 4096
#define FF 64
#define HH 128
#define NHD 4
#define HD 32
#define LL 3
#define CC 7
#define MAXD 96
#define HHB 128      // 32-row GEMM blocks
#define SPB 256      // S partials per channel (HHB blocks x 2 rowgroups)

// ---------------- device scratch ----------------
__device__ float g_h[2][NN * HH];
__device__ float g_hh[NN * HH];
__device__ float g_sup[NN * HH];
__device__ float g_att[NN * HH];
__device__ float g_ssrc[NN * NHD];
__device__ float g_sdst[NN * NHD];
__device__ float g_Spart[HH * SPB];
__device__ float g_S[HH];
__device__ int   g_cols[NN * MAXD];
__device__ int   g_cnt[NN];
__device__ float g_dinv[NN];
__device__ float g_mpart[HHB * HH];

// ---- shared helper: hh = hs(smem,32x128) @ attnW + Wb, epilogue ssrc/sdst/Spart ----
__device__ __forceinline__ void hh_phase(float* sA, const float* sB, int r0, int blkLocal,
                                         const float* __restrict__ Wl,
                                         const float* __restrict__ Wbl,
                                         const float* __restrict__ al) {
    int tid = threadIdx.x;
    int col = tid & 127, rg = tid >> 7;
    int head = col >> 5, d = col & 31;
    float acc[16];
#pragma unroll
    for (int i = 0; i < 16; i++) acc[i] = 0.0f;
    for (int kt = 0; kt < HH; kt += 32) {
        __syncthreads();
        for (int i = tid; i < 32 * HH; i += 256) {
            int k = i >> 7, cc = i & 127;
            sA[i] = Wl[(cc >> 5) * (HH * HD) + (kt + k) * HD + (cc & 31)];
        }
        __syncthreads();
#pragma unroll 8
        for (int k = 0; k < 32; k++) {
            float wv = sA[k * HH + col];
#pragma unroll
            for (int i = 0; i < 16; i++)
                acc[i] += sB[(rg * 16 + i) * HH + kt + k] * wv;
        }
    }
    float wb = Wbl[col];
    float asrc = al[head * 64 + d];
    float adst = al[head * 64 + 32 + d];
    float Sloc = 0.0f;
#pragma unroll 1
    for (int i = 0; i < 16; i++) {
        int r = r0 + rg * 16 + i;
        float v = acc[i] + wb;
        g_hh[r * HH + col] = v;
        Sloc += v;
        float vs = v * asrc, vd = v * adst;
#pragma unroll
        for (int off = 16; off; off >>= 1) {
            vs += __shfl_xor_sync(0xffffffffu, vs, off);
            vd += __shfl_xor_sync(0xffffffffu, vd, off);
        }
        if (d == 0) {
            g_ssrc[r * NHD + head] = vs;
            g_sdst[r * NHD + head] = vd;
        }
    }
    g_Spart[col * SPB + blkLocal * 2 + rg] = Sloc;
}

// ---------------- 1) fused: edge-list build + encoder + hh(layer0) ----------------
__global__ void k_build_enc_hh(const float* __restrict__ adj,
                               const float* __restrict__ x,
                               const float* __restrict__ W,
                               const float* __restrict__ b,
                               const float* __restrict__ aW0,
                               const float* __restrict__ aWb0,
                               const float* __restrict__ aa0) {
    __shared__ float xs[32 * FF];
    __shared__ float sA[32 * HH];
    __shared__ float sB[32 * HH];
    if (blockIdx.x < NN / 8) {
        int warp = (blockIdx.x * 256 + threadIdx.x) >> 5;
        int lane = threadIdx.x & 31;
        const float4* row = (const float4*)(adj + (size_t)warp * NN);
        int base = warp * MAXD;
        int cnt = 0;
        for (int c0 = 0; c0 < NN / 4; c0 += 32) {
            float4 v = row[c0 + lane];
            float vals[4] = {v.x, v.y, v.z, v.w};
#pragma unroll
            for (int k = 0; k < 4; k++) {
                unsigned m = __ballot_sync(0xffffffffu, vals[k] > 0.0f);
                if (vals[k] > 0.0f) {
                    int pos = cnt + __popc(m & ((1u << lane) - 1u));
                    if (pos < MAXD) g_cols[base + pos] = (c0 + lane) * 4 + k;
                }
                cnt += __popc(m);
            }
        }
        if (lane == 0) {
            if (cnt > MAXD) cnt = MAXD;
            g_cnt[warp] = cnt;
            g_dinv[warp] = rsqrtf((float)cnt + 1.0f);
        }
    } else {
        int blkLocal = blockIdx.x - NN / 8;
        int r0 = blkLocal * 32;
        int tid = threadIdx.x;
        int col = tid & 127, rg = tid >> 7;
        for (int i = tid; i < 32 * FF; i += 256) xs[i] = x[r0 * FF + i];
        float acc[16];
#pragma unroll
        for (int i = 0; i < 16; i++) acc[i] = 0.0f;
        for (int kt = 0; kt < FF; kt += 32) {
            __syncthreads();
            for (int i = tid; i < 32 * HH; i += 256)
                sA[i] = W[(kt + (i >> 7)) * HH + (i & 127)];
            __syncthreads();
#pragma unroll 8
            for (int k = 0; k < 32; k++) {
                float wv = sA[k * HH + col];
#pragma unroll
                for (int i = 0; i < 16; i++)
                    acc[i] += xs[(rg * 16 + i) * FF + kt + k] * wv;
            }
        }
        float bb = b[col];
        __syncthreads();
#pragma unroll
        for (int i = 0; i < 16; i++) {
            int r = r0 + rg * 16 + i;
            float v = fmaxf(acc[i] + bb, 0.0f);
            sB[(rg * 16 + i) * HH + col] = v;
            g_h[0][r * HH + col] = v;
        }
        hh_phase(sA, sB, r0, blkLocal, aW0, aWb0, aa0);
    }
}

// ---------------- 2) S reduce ----------------
__global__ void k_sred() {
    __shared__ float sm[4];
    int c = blockIdx.x, t = threadIdx.x;
    const float* p = g_Spart + c * SPB;
    float s = p[t] + p[t + 128];
#pragma unroll
    for (int off = 16; off; off >>= 1) s += __shfl_xor_sync(0xffffffffu, s, off);
    if ((t & 31) == 0) sm[t >> 5] = s;
    __syncthreads();
    if (t == 0) g_S[c] = sm[0] + sm[1] + sm[2] + sm[3];
}

// ---------------- 3) sparse: block per node, unroll-4 edge loop ----------------
__global__ void k_sparse(int ping, const float* __restrict__ abl) {
    int n = blockIdx.x, c = threadIdx.x;
    int head = c >> 5;
    __shared__ int   cols_s[MAXD];
    __shared__ float dinv_s[MAXD];
    __shared__ float w_s[MAXD * NHD];
    __shared__ float ss[NHD];
    const float* hin = g_h[ping];
    int E = g_cnt[n];
    if (c < NHD) ss[c] = g_ssrc[n * NHD + c] + abl[c];
    for (int e = c; e < E; e += HH) {
        int j = g_cols[n * MAXD + e];
        cols_s[e] = j;
        dinv_s[e] = g_dinv[j];
    }
    __syncthreads();
    for (int idx = c; idx < E * NHD; idx += HH) {
        int e = idx >> 2, h2 = idx & 3;
        w_s[idx] = expf(ss[h2] + g_sdst[cols_s[e] * NHD + h2]) - 1.0f;
    }
    __syncthreads();
    float di = g_dinv[n];
    float accg = di * hin[n * HH + c];
    float acca = g_S[c];
    float denom = (float)NN;
    int e = 0;
    for (; e + 4 <= E; e += 4) {
        int j0 = cols_s[e], j1 = cols_s[e + 1], j2 = cols_s[e + 2], j3 = cols_s[e + 3];
        float h0 = hin[j0 * HH + c], h1 = hin[j1 * HH + c];
        float h2 = hin[j2 * HH + c], h3 = hin[j3 * HH + c];
        float q0 = g_hh[j0 * HH + c], q1 = g_hh[j1 * HH + c];
        float q2 = g_hh[j2 * HH + c], q3 = g_hh[j3 * HH + c];
        float d0 = dinv_s[e], d1 = dinv_s[e + 1], d2 = dinv_s[e + 2], d3 = dinv_s[e + 3];
        float w0 = w_s[e * 4 + head], w1 = w_s[(e + 1) * 4 + head];
        float w2 = w_s[(e + 2) * 4 + head], w3 = w_s[(e + 3) * 4 + head];
        accg += d0 * h0; accg += d1 * h1; accg += d2 * h2; accg += d3 * h3;
        acca += w0 * q0; acca += w1 * q1; acca += w2 * q2; acca += w3 * q3;
        denom += w0 + w1 + w2 + w3;
    }
    for (; e < E; e++) {
        int j = cols_s[e];
        accg += dinv_s[e] * hin[j * HH + c];
        float w = w_s[e * 4 + head];
        acca += w * g_hh[j * HH + c];
        denom += w;
    }
    g_sup[n * HH + c] = di * accg;
    g_att[n * HH + c] = acca / denom;
}

// ---------------- 4) fused: combine GEMM + hh GEMM of next layer ----------------
__global__ void k_comb_hh(int ping, const float* __restrict__ Wl,
                          const float* __restrict__ bl,
                          const float* __restrict__ aWn,
                          const float* __restrict__ aWbn,
                          const float* __restrict__ aan) {
    __shared__ float sA[32 * HH];
    __shared__ float sB[32 * HH];
    float* hout = g_h[ping ^ 1];
    int tid = threadIdx.x;
    int col = tid & 127, rg = tid >> 7;
    int r0 = blockIdx.x * 32;
    for (int i = tid; i < 32 * HH; i += 256) sB[i] = g_sup[r0 * HH + i];
    float acc[16];
#pragma unroll
    for (int i = 0; i < 16; i++) acc[i] = 0.0f;
    for (int kt = 0; kt < HH; kt += 32) {
        __syncthreads();
        for (int i = tid; i < 32 * HH; i += 256) sA[i] = Wl[kt * HH + i];
        __syncthreads();
#pragma unroll 8
        for (int k = 0; k < 32; k++) {
            float w = sA[k * HH + col];
#pragma unroll
            for (int i = 0; i < 16; i++)
                acc[i] += sB[(rg * 16 + i) * HH + kt + k] * w;
        }
    }
    float b = bl[col];
    __syncthreads();
#pragma unroll
    for (int i = 0; i < 16; i++) {
        int r = r0 + rg * 16 + i;
        float v = fmaxf(acc[i] + b, 0.0f) + g_att[r * HH + col];
        v = fmaxf(v, 0.0f);
        sB[(rg * 16 + i) * HH + col] = v;
        hout[r * HH + col] = v;
    }
    hh_phase(sA, sB, r0, blockIdx.x, aWn, aWbn, aan);
}

// ---------------- 5) fused: final combine + classifier head + mean partials ----
__global__ void k_comb_head(int ping, const float* __restrict__ Wl,
                            const float* __restrict__ bl,
                            const float* __restrict__ W1, const float* __restrict__ b1,
                            const float* __restrict__ W2, const float* __restrict__ b2,
                            float* __restrict__ out_logits, float* __restrict__ out_h) {
    __shared__ float sA[32 * HH];
    __shared__ float sB[32 * HH];
    int tid = threadIdx.x;
    int col = tid & 127, rg = tid >> 7;
    int r0 = blockIdx.x * 32;
    for (int i = tid; i < 32 * HH; i += 256) sB[i] = g_sup[r0 * HH + i];
    float acc[16];
#pragma unroll
    for (int i = 0; i < 16; i++) acc[i] = 0.0f;
    for (int kt = 0; kt < HH; kt += 32) {
        __syncthreads();
        for (int i = tid; i < 32 * HH; i += 256) sA[i] = Wl[kt * HH + i];
        __syncthreads();
#pragma unroll 8
        for (int k = 0; k < 32; k++) {
            float w = sA[k * HH + col];
#pragma unroll
            for (int i = 0; i < 16; i++)
                acc[i] += sB[(rg * 16 + i) * HH + kt + k] * w;
        }
    }
    float b = bl[col];
    __syncthreads();
#pragma unroll
    for (int i = 0; i < 16; i++) {
        int r = r0 + rg * 16 + i;
        float v = fmaxf(acc[i] + b, 0.0f) + g_att[r * HH + col];
        v = fmaxf(v, 0.0f);
        sB[(rg * 16 + i) * HH + col] = v;
        out_h[r * HH + col] = v;
    }
    __syncthreads();
    // mean partials (first 128 threads sum the 32 rows of this block)
    if (tid < HH) {
        float s = 0.0f;
#pragma unroll 8
        for (int r = 0; r < 32; r++) s += sB[r * HH + tid];
        g_mpart[blockIdx.x * HH + tid] = s;
    }
    // t1 = relu(h @ W1 + b1) : 32x64, each thread -> 8 outputs
    {
        int c6 = tid & 63, rg4 = tid >> 6;
        float a8[8];
#pragma unroll
        for (int i = 0; i < 8; i++) a8[i] = b1[c6];
        for (int k = 0; k < HH; k++) {
            float wv = W1[k * 64 + c6];
#pragma unroll
            for (int i = 0; i < 8; i++)
                a8[i] += sB[(rg4 * 8 + i) * HH + k] * wv;
        }
        __syncthreads();
#pragma unroll
        for (int i = 0; i < 8; i++)
            sA[(rg4 * 8 + i) * 64 + c6] = fmaxf(a8[i], 0.0f);
    }
    __syncthreads();
    // logits = t1 @ W2 + b2 : 32x7
    if (tid < 32 * CC) {
        int r = tid / CC, q = tid - r * CC;
        float a = b2[q];
#pragma unroll 16
        for (int k = 0; k < 64; k++) a += sA[r * 64 + k] * W2[k * CC + q];
        out_logits[(r0 + r) * CC + q] = a;
    }
}

// ---------------- 6) contagion head ----------------
__global__ void k_cont(const float* __restrict__ W1, const float* __restrict__ b1,
                       const float* __restrict__ W2, const float* __restrict__ b2,
                       float* __restrict__ out_c) {
    __shared__ float ms[HH];
    __shared__ float t1[64];
    int c = threadIdx.x;
    float s = 0.0f;
    for (int b = 0; b < HHB; b++) s += g_mpart[b * HH + c];
    ms[c] = s * (1.0f / (float)NN);
    __syncthreads();
    if (c < 64) {
        float a = b1[c];
#pragma unroll 16
        for (int k = 0; k < HH; k++) a += ms[k] * W1[k * 64 + c];
        t1[c] = fmaxf(a, 0.0f);
    }
    __syncthreads();
    if (c == 0) {
        float a = b2[0];
        for (int k = 0; k < 64; k++) a += t1[k] * W2[k];
        out_c[0] = a;
    }
}

extern "C" void kernel_launch(void* const* d_in, const int* in_sizes, int n_in,
                              void* d_out, int out_size) {
    const float* x      = (const float*)d_in[0];
    const float* adj    = (const float*)d_in[1];
    const float* enc_W  = (const float*)d_in[2];
    const float* enc_b  = (const float*)d_in[3];
    const float* gcn_W  = (const float*)d_in[4];
    const float* gcn_b  = (const float*)d_in[5];
    const float* attn_W = (const float*)d_in[6];
    const float* attn_Wb= (const float*)d_in[7];
    const float* attn_a = (const float*)d_in[8];
    const float* attn_ab= (const float*)d_in[9];
    const float* cls_W1 = (const float*)d_in[10];
    const float* cls_b1 = (const float*)d_in[11];
    const float* cls_W2 = (const float*)d_in[12];
    const float* cls_b2 = (const float*)d_in[13];
    const float* con_W1 = (const float*)d_in[14];
    const float* con_b1 = (const float*)d_in[15];
    const float* con_W2 = (const float*)d_in[16];
    const float* con_b2 = (const float*)d_in[17];

    float* out = (float*)d_out;
    float* out_logits = out;
    float* out_h      = out + NN * CC;
    float* out_c      = out + NN * CC + NN * HH;

    k_build_enc_hh<<<NN / 8 + HHB, 256>>>(adj, x, enc_W, enc_b,
                                          attn_W, attn_Wb, attn_a);

    int ping = 0;
    for (int l = 0; l < LL; l++) {
        k_sred<<<HH, HH>>>();
        k_sparse<<<NN, HH>>>(ping, attn_ab + l * NHD);
        if (l < LL - 1) {
            k_comb_hh<<<HHB, 256>>>(ping, gcn_W + l * HH * HH, gcn_b + l * HH,
                                    attn_W + (l + 1) * NHD * HH * HD,
                                    attn_Wb + (l + 1) * NHD * HD,
                                    attn_a + (l + 1) * NHD * 2 * HD);
            ping ^= 1;
        } else {
            k_comb_head<<<HHB, 256>>>(ping, gcn_W + l * HH * HH, gcn_b + l * HH,
                                      cls_W1, cls_b1, cls_W2, cls_b2,
                                      out_logits, out_h);
        }
    }
    k_cont<<<1, HH>>>(con_W1, con_b1, con_W2, con_b2, out_c);
}

// round 5
// speedup vs baseline: 1.2172x; 1.2172x over previous
#include <cuda_runtime.h>
#include <math.h>

#define NN 4096
#define FF 64
#define HH 128
#define NHD 4
#define HD 32
#define LL 3
#define CC 7
#define MAXD 96
#define GB 256       // 16-row GEMM blocks
#define SPB 512      // S partials per channel (GB blocks x 2 rowgroups)

// ---------------- device scratch ----------------
__device__ float g_h[2][NN * HH];
__device__ float g_hh[NN * HH];
__device__ float g_sup[NN * HH];
__device__ float g_att[NN * HH];
__device__ float g_ssrc[NN * NHD];
__device__ float g_sdst[NN * NHD];
__device__ float g_Spart[HH * SPB];
__device__ float g_S[HH];
__device__ int   g_cols[NN * MAXD];
__device__ int   g_cnt[NN];
__device__ float g_dinv[NN];
__device__ float g_mpart[GB * HH];

// ---- helper: hh = sB(16x128) @ attnW + Wb, epilogue ssrc/sdst/Spart ----
__device__ __forceinline__ void hh_phase(float* sA, const float* sB, int r0, int blkLocal,
                                         const float* __restrict__ Wl,
                                         const float* __restrict__ Wbl,
                                         const float* __restrict__ al) {
    int tid = threadIdx.x;
    int col = tid & 127, rg = tid >> 7;
    int head = col >> 5, d = col & 31;
    float acc[8];
#pragma unroll
    for (int i = 0; i < 8; i++) acc[i] = 0.0f;
    for (int kt = 0; kt < HH; kt += 32) {
        __syncthreads();
        for (int i = tid; i < 32 * HH; i += 256) {
            int k = i >> 7, cc = i & 127;
            sA[i] = Wl[(cc >> 5) * (HH * HD) + (kt + k) * HD + (cc & 31)];
        }
        __syncthreads();
#pragma unroll 8
        for (int k = 0; k < 32; k++) {
            float wv = sA[k * HH + col];
#pragma unroll
            for (int i = 0; i < 8; i++)
                acc[i] += sB[(rg * 8 + i) * HH + kt + k] * wv;
        }
    }
    float wb = Wbl[col];
    float asrc = al[head * 64 + d];
    float adst = al[head * 64 + 32 + d];
    float Sloc = 0.0f;
#pragma unroll 1
    for (int i = 0; i < 8; i++) {
        int r = r0 + rg * 8 + i;
        float v = acc[i] + wb;
        g_hh[r * HH + col] = v;
        Sloc += v;
        float vs = v * asrc, vd = v * adst;
#pragma unroll
        for (int off = 16; off; off >>= 1) {
            vs += __shfl_xor_sync(0xffffffffu, vs, off);
            vd += __shfl_xor_sync(0xffffffffu, vd, off);
        }
        if (d == 0) {
            g_ssrc[r * NHD + head] = vs;
            g_sdst[r * NHD + head] = vd;
        }
    }
    g_Spart[col * SPB + blkLocal * 2 + rg] = Sloc;
}

// ---------------- 1) fused: edge-list build + encoder + hh(layer0) ----------------
__global__ void k_build_enc_hh(const float* __restrict__ adj,
                               const float* __restrict__ x,
                               const float* __restrict__ W,
                               const float* __restrict__ b,
                               const float* __restrict__ aW0,
                               const float* __restrict__ aWb0,
                               const float* __restrict__ aa0) {
    __shared__ float xs[16 * FF];
    __shared__ float sA[32 * HH];
    __shared__ float sB[16 * HH];
    if (blockIdx.x < NN / 8) {
        int warp = (blockIdx.x * 256 + threadIdx.x) >> 5;
        int lane = threadIdx.x & 31;
        const float4* row = (const float4*)(adj + (size_t)warp * NN);
        int base = warp * MAXD;
        int cnt = 0;
        for (int c0 = 0; c0 < NN / 4; c0 += 32) {
            float4 v = row[c0 + lane];
            float vals[4] = {v.x, v.y, v.z, v.w};
#pragma unroll
            for (int k = 0; k < 4; k++) {
                unsigned m = __ballot_sync(0xffffffffu, vals[k] > 0.0f);
                if (vals[k] > 0.0f) {
                    int pos = cnt + __popc(m & ((1u << lane) - 1u));
                    if (pos < MAXD) g_cols[base + pos] = (c0 + lane) * 4 + k;
                }
                cnt += __popc(m);
            }
        }
        if (lane == 0) {
            if (cnt > MAXD) cnt = MAXD;
            g_cnt[warp] = cnt;
            g_dinv[warp] = rsqrtf((float)cnt + 1.0f);
        }
    } else {
        int blkLocal = blockIdx.x - NN / 8;
        int r0 = blkLocal * 16;
        int tid = threadIdx.x;
        int col = tid & 127, rg = tid >> 7;
        for (int i = tid; i < 16 * FF; i += 256) xs[i] = x[r0 * FF + i];
        float acc[8];
#pragma unroll
        for (int i = 0; i < 8; i++) acc[i] = 0.0f;
        for (int kt = 0; kt < FF; kt += 32) {
            __syncthreads();
            for (int i = tid; i < 32 * HH; i += 256)
                sA[i] = W[(kt + (i >> 7)) * HH + (i & 127)];
            __syncthreads();
#pragma unroll 8
            for (int k = 0; k < 32; k++) {
                float wv = sA[k * HH + col];
#pragma unroll
                for (int i = 0; i < 8; i++)
                    acc[i] += xs[(rg * 8 + i) * FF + kt + k] * wv;
            }
        }
        float bb = b[col];
        __syncthreads();
#pragma unroll
        for (int i = 0; i < 8; i++) {
            int r = r0 + rg * 8 + i;
            float v = fmaxf(acc[i] + bb, 0.0f);
            sB[(rg * 8 + i) * HH + col] = v;
            g_h[0][r * HH + col] = v;
        }
        hh_phase(sA, sB, r0, blkLocal, aW0, aWb0, aa0);
    }
}

// ---------------- 2) S reduce ----------------
__global__ void k_sred() {
    __shared__ float sm[4];
    int c = blockIdx.x, t = threadIdx.x;
    const float* p = g_Spart + c * SPB;
    float s = p[t] + p[t + 128] + p[t + 256] + p[t + 384];
#pragma unroll
    for (int off = 16; off; off >>= 1) s += __shfl_xor_sync(0xffffffffu, s, off);
    if ((t & 31) == 0) sm[t >> 5] = s;
    __syncthreads();
    if (t == 0) g_S[c] = sm[0] + sm[1] + sm[2] + sm[3];
}

// ---------------- 3) sparse: block per node, unroll-4 edge loop ----------------
__global__ void k_sparse(int ping, const float* __restrict__ abl) {
    int n = blockIdx.x, c = threadIdx.x;
    int head = c >> 5;
    __shared__ int   cols_s[MAXD];
    __shared__ float dinv_s[MAXD];
    __shared__ float w_s[MAXD * NHD];
    __shared__ float ss[NHD];
    const float* hin = g_h[ping];
    int E = g_cnt[n];
    if (c < NHD) ss[c] = g_ssrc[n * NHD + c] + abl[c];
    for (int e = c; e < E; e += HH) {
        int j = g_cols[n * MAXD + e];
        cols_s[e] = j;
        dinv_s[e] = g_dinv[j];
    }
    __syncthreads();
    for (int idx = c; idx < E * NHD; idx += HH) {
        int e = idx >> 2, h2 = idx & 3;
        w_s[idx] = expf(ss[h2] + g_sdst[cols_s[e] * NHD + h2]) - 1.0f;
    }
    __syncthreads();
    float di = g_dinv[n];
    float accg = di * hin[n * HH + c];
    float acca = g_S[c];
    float denom = (float)NN;
    int e = 0;
    for (; e + 4 <= E; e += 4) {
        int j0 = cols_s[e], j1 = cols_s[e + 1], j2 = cols_s[e + 2], j3 = cols_s[e + 3];
        float h0 = hin[j0 * HH + c], h1 = hin[j1 * HH + c];
        float h2 = hin[j2 * HH + c], h3 = hin[j3 * HH + c];
        float q0 = g_hh[j0 * HH + c], q1 = g_hh[j1 * HH + c];
        float q2 = g_hh[j2 * HH + c], q3 = g_hh[j3 * HH + c];
        float d0 = dinv_s[e], d1 = dinv_s[e + 1], d2 = dinv_s[e + 2], d3 = dinv_s[e + 3];
        float w0 = w_s[e * 4 + head], w1 = w_s[(e + 1) * 4 + head];
        float w2 = w_s[(e + 2) * 4 + head], w3 = w_s[(e + 3) * 4 + head];
        accg += d0 * h0; accg += d1 * h1; accg += d2 * h2; accg += d3 * h3;
        acca += w0 * q0; acca += w1 * q1; acca += w2 * q2; acca += w3 * q3;
        denom += w0 + w1 + w2 + w3;
    }
    for (; e < E; e++) {
        int j = cols_s[e];
        accg += dinv_s[e] * hin[j * HH + c];
        float w = w_s[e * 4 + head];
        acca += w * g_hh[j * HH + c];
        denom += w;
    }
    g_sup[n * HH + c] = di * accg;
    g_att[n * HH + c] = acca / denom;
}

// ---------------- 4) fused: combine GEMM + hh GEMM of next layer ----------------
__global__ void k_comb_hh(int ping, const float* __restrict__ Wl,
                          const float* __restrict__ bl,
                          const float* __restrict__ aWn,
                          const float* __restrict__ aWbn,
                          const float* __restrict__ aan) {
    __shared__ float sA[32 * HH];
    __shared__ float sB[16 * HH];
    float* hout = g_h[ping ^ 1];
    int tid = threadIdx.x;
    int col = tid & 127, rg = tid >> 7;
    int r0 = blockIdx.x * 16;
    for (int i = tid; i < 16 * HH; i += 256) sB[i] = g_sup[r0 * HH + i];
    float acc[8];
#pragma unroll
    for (int i = 0; i < 8; i++) acc[i] = 0.0f;
    for (int kt = 0; kt < HH; kt += 32) {
        __syncthreads();
        for (int i = tid; i < 32 * HH; i += 256) sA[i] = Wl[kt * HH + i];
        __syncthreads();
#pragma unroll 8
        for (int k = 0; k < 32; k++) {
            float w = sA[k * HH + col];
#pragma unroll
            for (int i = 0; i < 8; i++)
                acc[i] += sB[(rg * 8 + i) * HH + kt + k] * w;
        }
    }
    float b = bl[col];
    __syncthreads();
#pragma unroll
    for (int i = 0; i < 8; i++) {
        int r = r0 + rg * 8 + i;
        float v = fmaxf(acc[i] + b, 0.0f) + g_att[r * HH + col];
        v = fmaxf(v, 0.0f);
        sB[(rg * 8 + i) * HH + col] = v;
        hout[r * HH + col] = v;
    }
    hh_phase(sA, sB, r0, blockIdx.x, aWn, aWbn, aan);
}

// ---------------- 5) fused: final combine + classifier head + mean partials ----
__global__ void k_comb_head(int ping, const float* __restrict__ Wl,
                            const float* __restrict__ bl,
                            const float* __restrict__ W1, const float* __restrict__ b1,
                            const float* __restrict__ W2, const float* __restrict__ b2,
                            float* __restrict__ out_logits, float* __restrict__ out_h) {
    __shared__ float sA[32 * HH];
    __shared__ float sB[16 * HH];
    int tid = threadIdx.x;
    int col = tid & 127, rg = tid >> 7;
    int r0 = blockIdx.x * 16;
    for (int i = tid; i < 16 * HH; i += 256) sB[i] = g_sup[r0 * HH + i];
    float acc[8];
#pragma unroll
    for (int i = 0; i < 8; i++) acc[i] = 0.0f;
    for (int kt = 0; kt < HH; kt += 32) {
        __syncthreads();
        for (int i = tid; i < 32 * HH; i += 256) sA[i] = Wl[kt * HH + i];
        __syncthreads();
#pragma unroll 8
        for (int k = 0; k < 32; k++) {
            float w = sA[k * HH + col];
#pragma unroll
            for (int i = 0; i < 8; i++)
                acc[i] += sB[(rg * 8 + i) * HH + kt + k] * w;
        }
    }
    float b = bl[col];
    __syncthreads();
#pragma unroll
    for (int i = 0; i < 8; i++) {
        int r = r0 + rg * 8 + i;
        float v = fmaxf(acc[i] + b, 0.0f) + g_att[r * HH + col];
        v = fmaxf(v, 0.0f);
        sB[(rg * 8 + i) * HH + col] = v;
        out_h[r * HH + col] = v;
    }
    __syncthreads();
    // mean partials
    if (tid < HH) {
        float s = 0.0f;
#pragma unroll 8
        for (int r = 0; r < 16; r++) s += sB[r * HH + tid];
        g_mpart[blockIdx.x * HH + tid] = s;
    }
    // t1 = relu(h @ W1 + b1) : 16x64, each thread (c6, rg4) -> 4 rows
    {
        int c6 = tid & 63, rg4 = tid >> 6;
        float a4[4];
#pragma unroll
        for (int i = 0; i < 4; i++) a4[i] = b1[c6];
        for (int k = 0; k < HH; k++) {
            float wv = W1[k * 64 + c6];
#pragma unroll
            for (int i = 0; i < 4; i++)
                a4[i] += sB[(rg4 * 4 + i) * HH + k] * wv;
        }
        __syncthreads();
#pragma unroll
        for (int i = 0; i < 4; i++)
            sA[(rg4 * 4 + i) * 64 + c6] = fmaxf(a4[i], 0.0f);
    }
    __syncthreads();
    // logits = t1 @ W2 + b2 : 16x7
    if (tid < 16 * CC) {
        int r = tid / CC, q = tid - r * CC;
        float a = b2[q];
#pragma unroll 16
        for (int k = 0; k < 64; k++) a += sA[r * 64 + k] * W2[k * CC + q];
        out_logits[(r0 + r) * CC + q] = a;
    }
}

// ---------------- 6) contagion head ----------------
__global__ void k_cont(const float* __restrict__ W1, const float* __restrict__ b1,
                       const float* __restrict__ W2, const float* __restrict__ b2,
                       float* __restrict__ out_c) {
    __shared__ float ms[HH];
    __shared__ float t1[64];
    int c = threadIdx.x;
    float s = 0.0f;
    for (int b = 0; b < GB; b++) s += g_mpart[b * HH + c];
    ms[c] = s * (1.0f / (float)NN);
    __syncthreads();
    if (c < 64) {
        float a = b1[c];
#pragma unroll 16
        for (int k = 0; k < HH; k++) a += ms[k] * W1[k * 64 + c];
        t1[c] = fmaxf(a, 0.0f);
    }
    __syncthreads();
    if (c == 0) {
        float a = b2[0];
        for (int k = 0; k < 64; k++) a += t1[k] * W2[k];
        out_c[0] = a;
    }
}

extern "C" void kernel_launch(void* const* d_in, const int* in_sizes, int n_in,
                              void* d_out, int out_size) {
    const float* x      = (const float*)d_in[0];
    const float* adj    = (const float*)d_in[1];
    const float* enc_W  = (const float*)d_in[2];
    const float* enc_b  = (const float*)d_in[3];
    const float* gcn_W  = (const float*)d_in[4];
    const float* gcn_b  = (const float*)d_in[5];
    const float* attn_W = (const float*)d_in[6];
    const float* attn_Wb= (const float*)d_in[7];
    const float* attn_a = (const float*)d_in[8];
    const float* attn_ab= (const float*)d_in[9];
    const float* cls_W1 = (const float*)d_in[10];
    const float* cls_b1 = (const float*)d_in[11];
    const float* cls_W2 = (const float*)d_in[12];
    const float* cls_b2 = (const float*)d_in[13];
    const float* con_W1 = (const float*)d_in[14];
    const float* con_b1 = (const float*)d_in[15];
    const float* con_W2 = (const float*)d_in[16];
    const float* con_b2 = (const float*)d_in[17];

    float* out = (float*)d_out;
    float* out_logits = out;
    float* out_h      = out + NN * CC;
    float* out_c      = out + NN * CC + NN * HH;

    k_build_enc_hh<<<NN / 8 + GB, 256>>>(adj, x, enc_W, enc_b,
                                         attn_W, attn_Wb, attn_a);

    int ping = 0;
    for (int l = 0; l < LL; l++) {
        k_sred<<<HH, HH>>>();
        k_sparse<<<NN, HH>>>(ping, attn_ab + l * NHD);
        if (l < LL - 1) {
            k_comb_hh<<<GB, 256>>>(ping, gcn_W + l * HH * HH, gcn_b + l * HH,
                                   attn_W + (l + 1) * NHD * HH * HD,
                                   attn_Wb + (l + 1) * NHD * HD,
                                   attn_a + (l + 1) * NHD * 2 * HD);
            ping ^= 1;
        } else {
            k_comb_head<<<GB, 256>>>(ping, gcn_W + l * HH * HH, gcn_b + l * HH,
                                     cls_W1, cls_b1, cls_W2, cls_b2,
                                     out_logits, out_h);
        }
    }
    k_cont<<<1, HH>>>(con_W1, con_b1, con_W2, con_b2, out_c);
}

// round 6
// speedup vs baseline: 1.4580x; 1.1979x over previous
#include <cuda_runtime.h>
#include <math.h>

#define NN 4096
#define FF 64
#define HH 128
#define NHD 4
#define HD 32
#define LL 3
#define CC 7
#define MAXD 96
#define GB 128      // 32-row GEMM blocks

// ---------------- device scratch ----------------
__device__ __align__(16) float g_h[2][NN * HH];
__device__ __align__(16) float g_hh[NN * HH];
__device__ __align__(16) float g_sup[NN * HH];
__device__ __align__(16) float g_att[NN * HH];
__device__ __align__(16) float g_ssrc[NN * NHD];
__device__ __align__(16) float g_sdst[NN * NHD];
__device__ __align__(16) float g_Spart[GB * HH];   // [blk][col]
__device__ __align__(16) float g_S[HH];
__device__ __align__(16) int   g_cols[NN * MAXD];
__device__ int   g_cnt[NN];
__device__ float g_dinv[NN];
__device__ __align__(16) float g_mpart[GB * HH];

// ---- register-tiled inner product over one 32-k tile ----
// sA: [k][col] (32x128), sB: rows with rowStride floats, k-contiguous.
// Thread (rt=warp 0..7, lane 0..31) owns rows rt*4..+3, cols lane*4..+3.
__device__ __forceinline__ void mm_inner(const float* sA, const float* sB,
                                         int rowStride, int ktOff,
                                         float acc[4][4], int rt, int lane) {
#pragma unroll
    for (int k4 = 0; k4 < 8; k4++) {
        int k = k4 * 4;
        float4 A0 = ((const float4*)sA)[(k + 0) * 32 + lane];
        float4 A1 = ((const float4*)sA)[(k + 1) * 32 + lane];
        float4 A2 = ((const float4*)sA)[(k + 2) * 32 + lane];
        float4 A3 = ((const float4*)sA)[(k + 3) * 32 + lane];
#pragma unroll
        for (int i = 0; i < 4; i++) {
            float4 bv = *(const float4*)(sB + (rt * 4 + i) * rowStride + ktOff + k);
            acc[i][0] = fmaf(bv.x, A0.x, acc[i][0]);
            acc[i][1] = fmaf(bv.x, A0.y, acc[i][1]);
            acc[i][2] = fmaf(bv.x, A0.z, acc[i][2]);
            acc[i][3] = fmaf(bv.x, A0.w, acc[i][3]);
            acc[i][0] = fmaf(bv.y, A1.x, acc[i][0]);
            acc[i][1] = fmaf(bv.y, A1.y, acc[i][1]);
            acc[i][2] = fmaf(bv.y, A1.z, acc[i][2]);
            acc[i][3] = fmaf(bv.y, A1.w, acc[i][3]);
            acc[i][0] = fmaf(bv.z, A2.x, acc[i][0]);
            acc[i][1] = fmaf(bv.z, A2.y, acc[i][1]);
            acc[i][2] = fmaf(bv.z, A2.z, acc[i][2]);
            acc[i][3] = fmaf(bv.z, A2.w, acc[i][3]);
            acc[i][0] = fmaf(bv.w, A3.x, acc[i][0]);
            acc[i][1] = fmaf(bv.w, A3.y, acc[i][1]);
            acc[i][2] = fmaf(bv.w, A3.z, acc[i][2]);
            acc[i][3] = fmaf(bv.w, A3.w, acc[i][3]);
        }
    }
}

// ---- hh phase: hh = sB(32x128) @ attnW + Wb, epilogue ssrc/sdst/Spart ----
__device__ __forceinline__ void hh_phase(float* sA, const float* sB, float* sP,
                                         int r0, int blk,
                                         const float* __restrict__ aW,
                                         const float* __restrict__ Wb,
                                         const float* __restrict__ al) {
    int tid = threadIdx.x, lane = tid & 31, rt = tid >> 5;
    float acc[4][4];
#pragma unroll
    for (int i = 0; i < 4; i++)
#pragma unroll
        for (int j = 0; j < 4; j++) acc[i][j] = 0.0f;
    for (int kt = 0; kt < HH; kt += 32) {
        __syncthreads();
        // sA[k][col] = aW[head][kt+k][d],  col = head*32+d
        for (int i4 = tid; i4 < 1024; i4 += 256) {
            int k = i4 >> 5, colq = i4 & 31;
            ((float4*)sA)[i4] = *(const float4*)(aW + (colq >> 3) * (HH * HD)
                                                 + (kt + k) * HD + ((colq & 7) << 2));
        }
        __syncthreads();
        mm_inner(sA, sB, HH, kt, acc, rt, lane);
    }
    int col0 = lane * 4;
    int head = col0 >> 5;
    float4 wb = *(const float4*)(Wb + col0);
    float4 as = *(const float4*)(al + head * 64 + (col0 & 31));
    float4 ad = *(const float4*)(al + head * 64 + 32 + (col0 & 31));
    float cs0 = 0.f, cs1 = 0.f, cs2 = 0.f, cs3 = 0.f;
#pragma unroll
    for (int i = 0; i < 4; i++) {
        int r = r0 + rt * 4 + i;
        float v0 = acc[i][0] + wb.x, v1 = acc[i][1] + wb.y;
        float v2 = acc[i][2] + wb.z, v3 = acc[i][3] + wb.w;
        *(float4*)(g_hh + r * HH + col0) = make_float4(v0, v1, v2, v3);
        cs0 += v0; cs1 += v1; cs2 += v2; cs3 += v3;
        float vs = v0 * as.x + v1 * as.y + v2 * as.z + v3 * as.w;
        float vd = v0 * ad.x + v1 * ad.y + v2 * ad.z + v3 * ad.w;
        vs += __shfl_xor_sync(0xffffffffu, vs, 1);
        vs += __shfl_xor_sync(0xffffffffu, vs, 2);
        vs += __shfl_xor_sync(0xffffffffu, vs, 4);
        vd += __shfl_xor_sync(0xffffffffu, vd, 1);
        vd += __shfl_xor_sync(0xffffffffu, vd, 2);
        vd += __shfl_xor_sync(0xffffffffu, vd, 4);
        if ((lane & 7) == 0) {
            g_ssrc[r * NHD + head] = vs;
            g_sdst[r * NHD + head] = vd;
        }
    }
    *(float4*)(sP + rt * HH + col0) = make_float4(cs0, cs1, cs2, cs3);
    __syncthreads();
    if (tid < HH) {
        float s = 0.0f;
#pragma unroll
        for (int w = 0; w < 8; w++) s += sP[w * HH + tid];
        g_Spart[blk * HH + tid] = s;
    }
}

// ---------------- 1) fused: edge-list build + encoder + hh(layer0) ----------------
__global__ void k_build_enc_hh(const float* __restrict__ adj,
                               const float* __restrict__ x,
                               const float* __restrict__ W,
                               const float* __restrict__ b,
                               const float* __restrict__ aW0,
                               const float* __restrict__ aWb0,
                               const float* __restrict__ aa0) {
    __shared__ float sm[10240];   // sA[4096] | sB[4096] | xs/sP[2048]
    float* sA = sm;
    float* sB = sm + 4096;
    float* xs = sm + 8192;
    float* sP = sm + 8192;
    if (blockIdx.x < NN / 8) {
        int warp = (blockIdx.x * 256 + threadIdx.x) >> 5;
        int lane = threadIdx.x & 31;
        const float4* row = (const float4*)(adj + (size_t)warp * NN);
        int base = warp * MAXD;
        int cnt = 0;
        for (int c0 = 0; c0 < NN / 4; c0 += 32) {
            float4 v = row[c0 + lane];
            float vals[4] = {v.x, v.y, v.z, v.w};
#pragma unroll
            for (int k = 0; k < 4; k++) {
                unsigned m = __ballot_sync(0xffffffffu, vals[k] > 0.0f);
                if (vals[k] > 0.0f) {
                    int pos = cnt + __popc(m & ((1u << lane) - 1u));
                    if (pos < MAXD) g_cols[base + pos] = (c0 + lane) * 4 + k;
                }
                cnt += __popc(m);
            }
        }
        if (lane == 0) {
            if (cnt > MAXD) cnt = MAXD;
            g_cnt[warp] = cnt;
            g_dinv[warp] = rsqrtf((float)cnt + 1.0f);
        }
    } else {
        int blk = blockIdx.x - NN / 8;
        int r0 = blk * 32;
        int tid = threadIdx.x, lane = tid & 31, rt = tid >> 5;
        for (int i4 = tid; i4 < 512; i4 += 256)
            ((float4*)xs)[i4] = ((const float4*)(x + r0 * FF))[i4];
        float acc[4][4];
#pragma unroll
        for (int i = 0; i < 4; i++)
#pragma unroll
            for (int j = 0; j < 4; j++) acc[i][j] = 0.0f;
        for (int kt = 0; kt < FF; kt += 32) {
            __syncthreads();
            for (int i4 = tid; i4 < 1024; i4 += 256)
                ((float4*)sA)[i4] = ((const float4*)(W + kt * HH))[i4];
            __syncthreads();
            mm_inner(sA, xs, FF, kt, acc, rt, lane);
        }
        int col0 = lane * 4;
        float4 bb = *(const float4*)(b + col0);
#pragma unroll
        for (int i = 0; i < 4; i++) {
            int r = r0 + rt * 4 + i;
            float4 v = make_float4(fmaxf(acc[i][0] + bb.x, 0.0f),
                                   fmaxf(acc[i][1] + bb.y, 0.0f),
                                   fmaxf(acc[i][2] + bb.z, 0.0f),
                                   fmaxf(acc[i][3] + bb.w, 0.0f));
            *(float4*)(sB + (rt * 4 + i) * HH + col0) = v;
            *(float4*)(g_h[0] + r * HH + col0) = v;
        }
        hh_phase(sA, sB, sP, r0, blk, aW0, aWb0, aa0);
    }
}

// ---------------- 2) S reduce: one block per channel ----------------
__global__ void k_sred() {
    __shared__ float sm[4];
    int c = blockIdx.x, t = threadIdx.x;
    float s = g_Spart[t * HH + c];
#pragma unroll
    for (int off = 16; off; off >>= 1) s += __shfl_xor_sync(0xffffffffu, s, off);
    if ((t & 31) == 0) sm[t >> 5] = s;
    __syncthreads();
    if (t == 0) g_S[c] = sm[0] + sm[1] + sm[2] + sm[3];
}

// ---------------- 3) sparse: block per node, unroll-4 edge loop ----------------
__global__ void k_sparse(int ping, const float* __restrict__ abl) {
    int n = blockIdx.x, c = threadIdx.x;
    int head = c >> 5;
    __shared__ int   cols_s[MAXD];
    __shared__ float dinv_s[MAXD];
    __shared__ float w_s[MAXD * NHD];
    __shared__ float ss[NHD];
    const float* hin = g_h[ping];
    int E = g_cnt[n];
    if (c < NHD) ss[c] = g_ssrc[n * NHD + c] + abl[c];
    for (int e = c; e < E; e += HH) {
        int j = g_cols[n * MAXD + e];
        cols_s[e] = j;
        dinv_s[e] = g_dinv[j];
    }
    __syncthreads();
    for (int idx = c; idx < E * NHD; idx += HH) {
        int e = idx >> 2, h2 = idx & 3;
        w_s[idx] = expf(ss[h2] + g_sdst[cols_s[e] * NHD + h2]) - 1.0f;
    }
    __syncthreads();
    float di = g_dinv[n];
    float accg = di * hin[n * HH + c];
    float acca = g_S[c];
    float denom = (float)NN;
    int e = 0;
    for (; e + 4 <= E; e += 4) {
        int j0 = cols_s[e], j1 = cols_s[e + 1], j2 = cols_s[e + 2], j3 = cols_s[e + 3];
        float h0 = hin[j0 * HH + c], h1 = hin[j1 * HH + c];
        float h2 = hin[j2 * HH + c], h3 = hin[j3 * HH + c];
        float q0 = g_hh[j0 * HH + c], q1 = g_hh[j1 * HH + c];
        float q2 = g_hh[j2 * HH + c], q3 = g_hh[j3 * HH + c];
        float d0 = dinv_s[e], d1 = dinv_s[e + 1], d2 = dinv_s[e + 2], d3 = dinv_s[e + 3];
        float w0 = w_s[e * 4 + head], w1 = w_s[(e + 1) * 4 + head];
        float w2 = w_s[(e + 2) * 4 + head], w3 = w_s[(e + 3) * 4 + head];
        accg += d0 * h0; accg += d1 * h1; accg += d2 * h2; accg += d3 * h3;
        acca += w0 * q0; acca += w1 * q1; acca += w2 * q2; acca += w3 * q3;
        denom += w0 + w1 + w2 + w3;
    }
    for (; e < E; e++) {
        int j = cols_s[e];
        accg += dinv_s[e] * hin[j * HH + c];
        float w = w_s[e * 4 + head];
        acca += w * g_hh[j * HH + c];
        denom += w;
    }
    g_sup[n * HH + c] = di * accg;
    g_att[n * HH + c] = acca / denom;
}

// ---------------- 4) fused: combine GEMM + next-layer hh GEMM ----------------
__global__ void k_comb_hh(int ping, const float* __restrict__ Wl,
                          const float* __restrict__ bl,
                          const float* __restrict__ aWn,
                          const float* __restrict__ aWbn,
                          const float* __restrict__ aan) {
    __shared__ float sm[9216];  // sA[4096] | sB[4096] | sP[1024]
    float* sA = sm;
    float* sB = sm + 4096;
    float* sP = sm + 8192;
    float* hout = g_h[ping ^ 1];
    int tid = threadIdx.x, lane = tid & 31, rt = tid >> 5;
    int blk = blockIdx.x, r0 = blk * 32;
    for (int i4 = tid; i4 < 1024; i4 += 256)
        ((float4*)sB)[i4] = ((const float4*)(g_sup + r0 * HH))[i4];
    float acc[4][4];
#pragma unroll
    for (int i = 0; i < 4; i++)
#pragma unroll
        for (int j = 0; j < 4; j++) acc[i][j] = 0.0f;
    for (int kt = 0; kt < HH; kt += 32) {
        __syncthreads();
        for (int i4 = tid; i4 < 1024; i4 += 256)
            ((float4*)sA)[i4] = ((const float4*)(Wl + kt * HH))[i4];
        __syncthreads();
        mm_inner(sA, sB, HH, kt, acc, rt, lane);
    }
    int col0 = lane * 4;
    float4 bb = *(const float4*)(bl + col0);
    __syncthreads();   // all warps done reading sB before overwrite
#pragma unroll
    for (int i = 0; i < 4; i++) {
        int r = r0 + rt * 4 + i;
        float4 at = *(const float4*)(g_att + r * HH + col0);
        float4 v;
        v.x = fmaxf(fmaxf(acc[i][0] + bb.x, 0.0f) + at.x, 0.0f);
        v.y = fmaxf(fmaxf(acc[i][1] + bb.y, 0.0f) + at.y, 0.0f);
        v.z = fmaxf(fmaxf(acc[i][2] + bb.z, 0.0f) + at.z, 0.0f);
        v.w = fmaxf(fmaxf(acc[i][3] + bb.w, 0.0f) + at.w, 0.0f);
        *(float4*)(sB + (rt * 4 + i) * HH + col0) = v;
        *(float4*)(hout + r * HH + col0) = v;
    }
    hh_phase(sA, sB, sP, r0, blk, aWn, aWbn, aan);
}

// ---------------- 5) fused: final combine + classifier head + mean partials ----
__global__ void k_comb_head(int ping, const float* __restrict__ Wl,
                            const float* __restrict__ bl,
                            const float* __restrict__ W1, const float* __restrict__ b1,
                            const float* __restrict__ W2, const float* __restrict__ b2,
                            float* __restrict__ out_logits, float* __restrict__ out_h) {
    __shared__ float sm[8192];  // sA[4096] | sB[4096]
    float* sA = sm;
    float* sB = sm + 4096;
    int tid = threadIdx.x, lane = tid & 31, rt = tid >> 5;
    int blk = blockIdx.x, r0 = blk * 32;
    for (int i4 = tid; i4 < 1024; i4 += 256)
        ((float4*)sB)[i4] = ((const float4*)(g_sup + r0 * HH))[i4];
    float acc[4][4];
#pragma unroll
    for (int i = 0; i < 4; i++)
#pragma unroll
        for (int j = 0; j < 4; j++) acc[i][j] = 0.0f;
    for (int kt = 0; kt < HH; kt += 32) {
        __syncthreads();
        for (int i4 = tid; i4 < 1024; i4 += 256)
            ((float4*)sA)[i4] = ((const float4*)(Wl + kt * HH))[i4];
        __syncthreads();
        mm_inner(sA, sB, HH, kt, acc, rt, lane);
    }
    int col0 = lane * 4;
    float4 bb = *(const float4*)(bl + col0);
    __syncthreads();
#pragma unroll
    for (int i = 0; i < 4; i++) {
        int r = r0 + rt * 4 + i;
        float4 at = *(const float4*)(g_att + r * HH + col0);
        float4 v;
        v.x = fmaxf(fmaxf(acc[i][0] + bb.x, 0.0f) + at.x, 0.0f);
        v.y = fmaxf(fmaxf(acc[i][1] + bb.y, 0.0f) + at.y, 0.0f);
        v.z = fmaxf(fmaxf(acc[i][2] + bb.z, 0.0f) + at.z, 0.0f);
        v.w = fmaxf(fmaxf(acc[i][3] + bb.w, 0.0f) + at.w, 0.0f);
        *(float4*)(sB + (rt * 4 + i) * HH + col0) = v;
        *(float4*)(out_h + r * HH + col0) = v;
    }
    __syncthreads();
    // mean partials
    if (tid < HH) {
        float s = 0.0f;
#pragma unroll 8
        for (int r = 0; r < 32; r++) s += sB[r * HH + tid];
        g_mpart[blk * HH + tid] = s;
    }
    // t1 = relu(h @ W1 + b1): 32x64; thread (c6, rg) -> 8 rows
    {
        int c6 = tid & 63, rg = tid >> 6;
        float a8[8];
#pragma unroll
        for (int i = 0; i < 8; i++) a8[i] = b1[c6];
        for (int k = 0; k < HH; k++) {
            float wv = W1[k * 64 + c6];
#pragma unroll
            for (int i = 0; i < 8; i++)
                a8[i] += sB[(rg * 8 + i) * HH + k] * wv;
        }
#pragma unroll
        for (int i = 0; i < 8; i++)
            sA[(rg * 8 + i) * 64 + c6] = fmaxf(a8[i], 0.0f);
    }
    __syncthreads();
    // logits = t1 @ W2 + b2: 32x7
    if (tid < 32 * CC) {
        int r = tid / CC, q = tid - r * CC;
        float a = b2[q];
#pragma unroll 16
        for (int k = 0; k < 64; k++) a += sA[r * 64 + k] * W2[k * CC + q];
        out_logits[(r0 + r) * CC + q] = a;
    }
}

// ---------------- 6) contagion head ----------------
__global__ void k_cont(const float* __restrict__ W1, const float* __restrict__ b1,
                       const float* __restrict__ W2, const float* __restrict__ b2,
                       float* __restrict__ out_c) {
    __shared__ float ms[HH];
    __shared__ float t1[64];
    int c = threadIdx.x;
    float s = 0.0f;
    for (int b = 0; b < GB; b++) s += g_mpart[b * HH + c];
    ms[c] = s * (1.0f / (float)NN);
    __syncthreads();
    if (c < 64) {
        float a = b1[c];
#pragma unroll 16
        for (int k = 0; k < HH; k++) a += ms[k] * W1[k * 64 + c];
        t1[c] = fmaxf(a, 0.0f);
    }
    __syncthreads();
    if (c == 0) {
        float a = b2[0];
        for (int k = 0; k < 64; k++) a += t1[k] * W2[k];
        out_c[0] = a;
    }
}

extern "C" void kernel_launch(void* const* d_in, const int* in_sizes, int n_in,
                              void* d_out, int out_size) {
    const float* x      = (const float*)d_in[0];
    const float* adj    = (const float*)d_in[1];
    const float* enc_W  = (const float*)d_in[2];
    const float* enc_b  = (const float*)d_in[3];
    const float* gcn_W  = (const float*)d_in[4];
    const float* gcn_b  = (const float*)d_in[5];
    const float* attn_W = (const float*)d_in[6];
    const float* attn_Wb= (const float*)d_in[7];
    const float* attn_a = (const float*)d_in[8];
    const float* attn_ab= (const float*)d_in[9];
    const float* cls_W1 = (const float*)d_in[10];
    const float* cls_b1 = (const float*)d_in[11];
    const float* cls_W2 = (const float*)d_in[12];
    const float* cls_b2 = (const float*)d_in[13];
    const float* con_W1 = (const float*)d_in[14];
    const float* con_b1 = (const float*)d_in[15];
    const float* con_W2 = (const float*)d_in[16];
    const float* con_b2 = (const float*)d_in[17];

    float* out = (float*)d_out;
    float* out_logits = out;
    float* out_h      = out + NN * CC;
    float* out_c      = out + NN * CC + NN * HH;

    k_build_enc_hh<<<NN / 8 + GB, 256>>>(adj, x, enc_W, enc_b,
                                         attn_W, attn_Wb, attn_a);

    int ping = 0;
    for (int l = 0; l < LL; l++) {
        k_sred<<<HH, HH>>>();
        k_sparse<<<NN, HH>>>(ping, attn_ab + l * NHD);
        if (l < LL - 1) {
            k_comb_hh<<<GB, 256>>>(ping, gcn_W + l * HH * HH, gcn_b + l * HH,
                                   attn_W + (l + 1) * NHD * HH * HD,
                                   attn_Wb + (l + 1) * NHD * HD,
                                   attn_a + (l + 1) * NHD * 2 * HD);
            ping ^= 1;
        } else {
            k_comb_head<<<GB, 256>>>(ping, gcn_W + l * HH * HH, gcn_b + l * HH,
                                     cls_W1, cls_b1, cls_W2, cls_b2,
                                     out_logits, out_h);
        }
    }
    k_cont<<<1, HH>>>(con_W1, con_b1, con_W2, con_b2, out_c);
}

// round 8
// speedup vs baseline: 1.5515x; 1.0641x over previous
#include <cuda_runtime.h>
#include <math.h>

#define NN 4096
#define FF 64
#define HH 128
#define NHD 4
#define HD 32
#define LL 3
#define CC 7
#define MAXD 96
#define GB 128      // 32-row GEMM blocks

// ---------------- device scratch ----------------
__device__ __align__(16) float g_h[2][NN * HH];
__device__ __align__(16) float g_hh[NN * HH];
__device__ __align__(16) float g_sup[NN * HH];
__device__ __align__(16) float g_att[NN * HH];
__device__ __align__(16) float g_ssrc[NN * NHD];
__device__ __align__(16) float g_sdst[NN * NHD];
__device__ __align__(16) float g_Spart[GB * HH];   // [blk][col]
__device__ __align__(16) float g_S[HH];
__device__ __align__(16) int   g_cols[NN * MAXD];
__device__ int   g_cnt[NN];
__device__ float g_dinv[NN];
__device__ __align__(16) float g_mpart[GB * HH];

// ---- register-tiled full-K GEMM: sW [k][col] (KD x 128), sB rows k-contiguous ----
// Thread (rt=warp 0..7, lane) owns rows rt*4..+3, cols lane*4..+3.
template <int KD, int RS>
__device__ __forceinline__ void mm_full(const float* sW, const float* sB,
                                        float acc[4][4], int rt, int lane) {
#pragma unroll 4
    for (int k = 0; k < KD; k += 4) {
        float4 A0 = ((const float4*)sW)[(k + 0) * 32 + lane];
        float4 A1 = ((const float4*)sW)[(k + 1) * 32 + lane];
        float4 A2 = ((const float4*)sW)[(k + 2) * 32 + lane];
        float4 A3 = ((const float4*)sW)[(k + 3) * 32 + lane];
#pragma unroll
        for (int i = 0; i < 4; i++) {
            float4 bv = *(const float4*)(sB + (rt * 4 + i) * RS + k);
            acc[i][0] = fmaf(bv.x, A0.x, acc[i][0]);
            acc[i][1] = fmaf(bv.x, A0.y, acc[i][1]);
            acc[i][2] = fmaf(bv.x, A0.z, acc[i][2]);
            acc[i][3] = fmaf(bv.x, A0.w, acc[i][3]);
            acc[i][0] = fmaf(bv.y, A1.x, acc[i][0]);
            acc[i][1] = fmaf(bv.y, A1.y, acc[i][1]);
            acc[i][2] = fmaf(bv.y, A1.z, acc[i][2]);
            acc[i][3] = fmaf(bv.y, A1.w, acc[i][3]);
            acc[i][0] = fmaf(bv.z, A2.x, acc[i][0]);
            acc[i][1] = fmaf(bv.z, A2.y, acc[i][1]);
            acc[i][2] = fmaf(bv.z, A2.z, acc[i][2]);
            acc[i][3] = fmaf(bv.z, A2.w, acc[i][3]);
            acc[i][0] = fmaf(bv.w, A3.x, acc[i][0]);
            acc[i][1] = fmaf(bv.w, A3.y, acc[i][1]);
            acc[i][2] = fmaf(bv.w, A3.z, acc[i][2]);
            acc[i][3] = fmaf(bv.w, A3.w, acc[i][3]);
        }
    }
}

// ---- load attn_W[head][k][d] into sW2[k][col=head*32+d] (4096 float4) ----
__device__ __forceinline__ void load_attnW(float* sW2, const float* __restrict__ aW,
                                           int tid) {
    for (int i4 = tid; i4 < 4096; i4 += 256) {
        int k = i4 >> 5, colq = i4 & 31;
        ((float4*)sW2)[i4] = *(const float4*)(aW + (colq >> 3) * (HH * HD)
                                              + k * HD + ((colq & 7) << 2));
    }
}

// ---- hh epilogue+GEMM: hh = sB @ sW2 + Wb; ssrc/sdst/Spart ----
__device__ __forceinline__ void hh_phase(const float* sW2, const float* sB, float* sP,
                                         int r0, int blk,
                                         const float* __restrict__ Wb,
                                         const float* __restrict__ al) {
    int tid = threadIdx.x, lane = tid & 31, rt = tid >> 5;
    float acc[4][4];
#pragma unroll
    for (int i = 0; i < 4; i++)
#pragma unroll
        for (int j = 0; j < 4; j++) acc[i][j] = 0.0f;
    mm_full<HH, HH>(sW2, sB, acc, rt, lane);
    int col0 = lane * 4;
    int head = col0 >> 5;
    float4 wb = *(const float4*)(Wb + col0);
    float4 as = *(const float4*)(al + head * 64 + (col0 & 31));
    float4 ad = *(const float4*)(al + head * 64 + 32 + (col0 & 31));
    float cs0 = 0.f, cs1 = 0.f, cs2 = 0.f, cs3 = 0.f;
#pragma unroll
    for (int i = 0; i < 4; i++) {
        int r = r0 + rt * 4 + i;
        float v0 = acc[i][0] + wb.x, v1 = acc[i][1] + wb.y;
        float v2 = acc[i][2] + wb.z, v3 = acc[i][3] + wb.w;
        *(float4*)(g_hh + r * HH + col0) = make_float4(v0, v1, v2, v3);
        cs0 += v0; cs1 += v1; cs2 += v2; cs3 += v3;
        float vs = v0 * as.x + v1 * as.y + v2 * as.z + v3 * as.w;
        float vd = v0 * ad.x + v1 * ad.y + v2 * ad.z + v3 * ad.w;
        vs += __shfl_xor_sync(0xffffffffu, vs, 1);
        vs += __shfl_xor_sync(0xffffffffu, vs, 2);
        vs += __shfl_xor_sync(0xffffffffu, vs, 4);
        vd += __shfl_xor_sync(0xffffffffu, vd, 1);
        vd += __shfl_xor_sync(0xffffffffu, vd, 2);
        vd += __shfl_xor_sync(0xffffffffu, vd, 4);
        if ((lane & 7) == 0) {
            g_ssrc[r * NHD + head] = vs;
            g_sdst[r * NHD + head] = vd;
        }
    }
    *(float4*)(sP + rt * HH + col0) = make_float4(cs0, cs1, cs2, cs3);
    __syncthreads();
    if (tid < HH) {
        float s = 0.0f;
#pragma unroll
        for (int w = 0; w < 8; w++) s += sP[w * HH + tid];
        g_Spart[blk * HH + tid] = s;
    }
}

// ---------------- 1) edge-list build (own kernel: needs high occupancy) ----------
__global__ void k_build(const float* __restrict__ adj) {
    int warp = (blockIdx.x * blockDim.x + threadIdx.x) >> 5;
    int lane = threadIdx.x & 31;
    const float4* row = (const float4*)(adj + (size_t)warp * NN);
    int base = warp * MAXD;
    int cnt = 0;
    for (int c0 = 0; c0 < NN / 4; c0 += 32) {
        float4 v = row[c0 + lane];
        float vals[4] = {v.x, v.y, v.z, v.w};
#pragma unroll
        for (int k = 0; k < 4; k++) {
            unsigned m = __ballot_sync(0xffffffffu, vals[k] > 0.0f);
            if (vals[k] > 0.0f) {
                int pos = cnt + __popc(m & ((1u << lane) - 1u));
                if (pos < MAXD) g_cols[base + pos] = (c0 + lane) * 4 + k;
            }
            cnt += __popc(m);
        }
    }
    if (lane == 0) {
        if (cnt > MAXD) cnt = MAXD;
        g_cnt[warp] = cnt;
        g_dinv[warp] = rsqrtf((float)cnt + 1.0f);
    }
}

// ---------------- 2) fused encoder GEMM + hh(layer0), full-W smem ----------------
// smem: sWe[8192] | sW2[16384] | xs[2048] | sB[4096] | sP[1024] = 31744 floats
__global__ void k_enc_hh(const float* __restrict__ x,
                         const float* __restrict__ W,
                         const float* __restrict__ b,
                         const float* __restrict__ aW0,
                         const float* __restrict__ aWb0,
                         const float* __restrict__ aa0) {
    extern __shared__ float sm[];
    float* sWe = sm;
    float* sW2 = sm + 8192;
    float* xs  = sm + 24576;
    float* sB  = sm + 26624;
    float* sP  = sm + 30720;
    int tid = threadIdx.x, lane = tid & 31, rt = tid >> 5;
    int blk = blockIdx.x, r0 = blk * 32;
    for (int i4 = tid; i4 < 2048; i4 += 256)
        ((float4*)sWe)[i4] = ((const float4*)W)[i4];
    load_attnW(sW2, aW0, tid);
    for (int i4 = tid; i4 < 512; i4 += 256)
        ((float4*)xs)[i4] = ((const float4*)(x + r0 * FF))[i4];
    __syncthreads();
    float acc[4][4];
#pragma unroll
    for (int i = 0; i < 4; i++)
#pragma unroll
        for (int j = 0; j < 4; j++) acc[i][j] = 0.0f;
    mm_full<FF, FF>(sWe, xs, acc, rt, lane);
    int col0 = lane * 4;
    float4 bb = *(const float4*)(b + col0);
#pragma unroll
    for (int i = 0; i < 4; i++) {
        int r = r0 + rt * 4 + i;
        float4 v = make_float4(fmaxf(acc[i][0] + bb.x, 0.0f),
                               fmaxf(acc[i][1] + bb.y, 0.0f),
                               fmaxf(acc[i][2] + bb.z, 0.0f),
                               fmaxf(acc[i][3] + bb.w, 0.0f));
        *(float4*)(sB + (rt * 4 + i) * HH + col0) = v;
        *(float4*)(g_h[0] + r * HH + col0) = v;
    }
    __syncthreads();
    hh_phase(sW2, sB, sP, r0, blk, aWb0, aa0);
}

// ---------------- 3) S reduce ----------------
__global__ void k_sred() {
    __shared__ float sm[4];
    int c = blockIdx.x, t = threadIdx.x;
    float s = g_Spart[t * HH + c];
#pragma unroll
    for (int off = 16; off; off >>= 1) s += __shfl_xor_sync(0xffffffffu, s, off);
    if ((t & 31) == 0) sm[t >> 5] = s;
    __syncthreads();
    if (t == 0) g_S[c] = sm[0] + sm[1] + sm[2] + sm[3];
}

// ---------------- 4) sparse: block per node ----------------
__global__ void k_sparse(int ping, const float* __restrict__ abl) {
    int n = blockIdx.x, c = threadIdx.x;
    int head = c >> 5;
    __shared__ int   cols_s[MAXD];
    __shared__ float dinv_s[MAXD];
    __shared__ float w_s[MAXD * NHD];
    __shared__ float ss[NHD];
    const float* hin = g_h[ping];
    int E = g_cnt[n];
    if (c < NHD) ss[c] = g_ssrc[n * NHD + c] + abl[c];
    for (int e = c; e < E; e += HH) {
        int j = g_cols[n * MAXD + e];
        cols_s[e] = j;
        dinv_s[e] = g_dinv[j];
    }
    __syncthreads();
    for (int idx = c; idx < E * NHD; idx += HH) {
        int e = idx >> 2, h2 = idx & 3;
        w_s[idx] = expf(ss[h2] + g_sdst[cols_s[e] * NHD + h2]) - 1.0f;
    }
    __syncthreads();
    float di = g_dinv[n];
    float accg = di * hin[n * HH + c];
    float acca = g_S[c];
    float denom = (float)NN;
    int e = 0;
    for (; e + 4 <= E; e += 4) {
        int j0 = cols_s[e], j1 = cols_s[e + 1], j2 = cols_s[e + 2], j3 = cols_s[e + 3];
        float h0 = hin[j0 * HH + c], h1 = hin[j1 * HH + c];
        float h2 = hin[j2 * HH + c], h3 = hin[j3 * HH + c];
        float q0 = g_hh[j0 * HH + c], q1 = g_hh[j1 * HH + c];
        float q2 = g_hh[j2 * HH + c], q3 = g_hh[j3 * HH + c];
        float d0 = dinv_s[e], d1 = dinv_s[e + 1], d2 = dinv_s[e + 2], d3 = dinv_s[e + 3];
        float w0 = w_s[e * 4 + head], w1 = w_s[(e + 1) * 4 + head];
        float w2 = w_s[(e + 2) * 4 + head], w3 = w_s[(e + 3) * 4 + head];
        accg += d0 * h0; accg += d1 * h1; accg += d2 * h2; accg += d3 * h3;
        acca += w0 * q0; acca += w1 * q1; acca += w2 * q2; acca += w3 * q3;
        denom += w0 + w1 + w2 + w3;
    }
    for (; e < E; e++) {
        int j = cols_s[e];
        accg += dinv_s[e] * hin[j * HH + c];
        float w = w_s[e * 4 + head];
        acca += w * g_hh[j * HH + c];
        denom += w;
    }
    g_sup[n * HH + c] = di * accg;
    g_att[n * HH + c] = acca / denom;
}

// ---------------- 5) fused combine GEMM + next-layer hh GEMM (full-W smem) -------
// smem: sW1[16384] | sW2[16384] | sB[4096] | sP[1024] = 37888 floats
__global__ void k_comb_hh(int ping, const float* __restrict__ Wl,
                          const float* __restrict__ bl,
                          const float* __restrict__ aWn,
                          const float* __restrict__ aWbn,
                          const float* __restrict__ aan) {
    extern __shared__ float sm[];
    float* sW1 = sm;
    float* sW2 = sm + 16384;
    float* sB  = sm + 32768;
    float* sP  = sm + 36864;
    float* hout = g_h[ping ^ 1];
    int tid = threadIdx.x, lane = tid & 31, rt = tid >> 5;
    int blk = blockIdx.x, r0 = blk * 32;
    for (int i4 = tid; i4 < 4096; i4 += 256)
        ((float4*)sW1)[i4] = ((const float4*)Wl)[i4];
    load_attnW(sW2, aWn, tid);
    for (int i4 = tid; i4 < 1024; i4 += 256)
        ((float4*)sB)[i4] = ((const float4*)(g_sup + r0 * HH))[i4];
    __syncthreads();
    float acc[4][4];
#pragma unroll
    for (int i = 0; i < 4; i++)
#pragma unroll
        for (int j = 0; j < 4; j++) acc[i][j] = 0.0f;
    mm_full<HH, HH>(sW1, sB, acc, rt, lane);
    int col0 = lane * 4;
    float4 bb = *(const float4*)(bl + col0);
    __syncthreads();   // everyone done reading sB
#pragma unroll
    for (int i = 0; i < 4; i++) {
        int r = r0 + rt * 4 + i;
        float4 at = *(const float4*)(g_att + r * HH + col0);
        float4 v;
        v.x = fmaxf(fmaxf(acc[i][0] + bb.x, 0.0f) + at.x, 0.0f);
        v.y = fmaxf(fmaxf(acc[i][1] + bb.y, 0.0f) + at.y, 0.0f);
        v.z = fmaxf(fmaxf(acc[i][2] + bb.z, 0.0f) + at.z, 0.0f);
        v.w = fmaxf(fmaxf(acc[i][3] + bb.w, 0.0f) + at.w, 0.0f);
        *(float4*)(sB + (rt * 4 + i) * HH + col0) = v;
        *(float4*)(hout + r * HH + col0) = v;
    }
    __syncthreads();
    hh_phase(sW2, sB, sP, r0, blk, aWbn, aan);
}

// ---------------- 6) fused final combine + classifier head + mean partials -------
// smem: sW1[16384] | sB[4096] = 20480 floats (sW1 reused for t1)
__global__ void k_comb_head(int ping, const float* __restrict__ Wl,
                            const float* __restrict__ bl,
                            const float* __restrict__ W1, const float* __restrict__ b1,
                            const float* __restrict__ W2, const float* __restrict__ b2,
                            float* __restrict__ out_logits, float* __restrict__ out_h) {
    extern __shared__ float sm[];
    float* sW1 = sm;
    float* sB  = sm + 16384;
    int tid = threadIdx.x, lane = tid & 31, rt = tid >> 5;
    int blk = blockIdx.x, r0 = blk * 32;
    for (int i4 = tid; i4 < 4096; i4 += 256)
        ((float4*)sW1)[i4] = ((const float4*)Wl)[i4];
    for (int i4 = tid; i4 < 1024; i4 += 256)
        ((float4*)sB)[i4] = ((const float4*)(g_sup + r0 * HH))[i4];
    __syncthreads();
    float acc[4][4];
#pragma unroll
    for (int i = 0; i < 4; i++)
#pragma unroll
        for (int j = 0; j < 4; j++) acc[i][j] = 0.0f;
    mm_full<HH, HH>(sW1, sB, acc, rt, lane);
    int col0 = lane * 4;
    float4 bb = *(const float4*)(bl + col0);
    __syncthreads();
#pragma unroll
    for (int i = 0; i < 4; i++) {
        int r = r0 + rt * 4 + i;
        float4 at = *(const float4*)(g_att + r * HH + col0);
        float4 v;
        v.x = fmaxf(fmaxf(acc[i][0] + bb.x, 0.0f) + at.x, 0.0f);
        v.y = fmaxf(fmaxf(acc[i][1] + bb.y, 0.0f) + at.y, 0.0f);
        v.z = fmaxf(fmaxf(acc[i][2] + bb.z, 0.0f) + at.z, 0.0f);
        v.w = fmaxf(fmaxf(acc[i][3] + bb.w, 0.0f) + at.w, 0.0f);
        *(float4*)(sB + (rt * 4 + i) * HH + col0) = v;
        *(float4*)(out_h + r * HH + col0) = v;
    }
    __syncthreads();
    // mean partials
    if (tid < HH) {
        float s = 0.0f;
#pragma unroll 8
        for (int r = 0; r < 32; r++) s += sB[r * HH + tid];
        g_mpart[blk * HH + tid] = s;
    }
    // t1 = relu(h @ W1 + b1): 32x64; thread (c6, rg) -> 8 rows; stored in sW1
    {
        int c6 = tid & 63, rg = tid >> 6;
        float a8[8];
#pragma unroll
        for (int i = 0; i < 8; i++) a8[i] = b1[c6];
        for (int k = 0; k < HH; k++) {
            float wv = W1[k * 64 + c6];
#pragma unroll
            for (int i = 0; i < 8; i++)
                a8[i] += sB[(rg * 8 + i) * HH + k] * wv;
        }
        __syncthreads();
#pragma unroll
        for (int i = 0; i < 8; i++)
            sW1[(rg * 8 + i) * 64 + c6] = fmaxf(a8[i], 0.0f);
    }
    __syncthreads();
    if (tid < 32 * CC) {
        int r = tid / CC, q = tid - r * CC;
        float a = b2[q];
#pragma unroll 16
        for (int k = 0; k < 64; k++) a += sW1[r * 64 + k] * W2[k * CC + q];
        out_logits[(r0 + r) * CC + q] = a;
    }
}

// ---------------- 7) contagion head ----------------
__global__ void k_cont(const float* __restrict__ W1, const float* __restrict__ b1,
                       const float* __restrict__ W2, const float* __restrict__ b2,
                       float* __restrict__ out_c) {
    __shared__ float ms[HH];
    __shared__ float t1[64];
    int c = threadIdx.x;
    float s = 0.0f;
    for (int b = 0; b < GB; b++) s += g_mpart[b * HH + c];
    ms[c] = s * (1.0f / (float)NN);
    __syncthreads();
    if (c < 64) {
        float a = b1[c];
#pragma unroll 16
        for (int k = 0; k < HH; k++) a += ms[k] * W1[k * 64 + c];
        t1[c] = fmaxf(a, 0.0f);
    }
    __syncthreads();
    if (c == 0) {
        float a = b2[0];
        for (int k = 0; k < 64; k++) a += t1[k] * W2[k];
        out_c[0] = a;
    }
}

extern "C" void kernel_launch(void* const* d_in, const int* in_sizes, int n_in,
                              void* d_out, int out_size) {
    const float* x      = (const float*)d_in[0];
    const float* adj    = (const float*)d_in[1];
    const float* enc_W  = (const float*)d_in[2];
    const float* enc_b  = (const float*)d_in[3];
    const float* gcn_W  = (const float*)d_in[4];
    const float* gcn_b  = (const float*)d_in[5];
    const float* attn_W = (const float*)d_in[6];
    const float* attn_Wb= (const float*)d_in[7];
    const float* attn_a = (const float*)d_in[8];
    const float* attn_ab= (const float*)d_in[9];
    const float* cls_W1 = (const float*)d_in[10];
    const float* cls_b1 = (const float*)d_in[11];
    const float* cls_W2 = (const float*)d_in[12];
    const float* cls_b2 = (const float*)d_in[13];
    const float* con_W1 = (const float*)d_in[14];
    const float* con_b1 = (const float*)d_in[15];
    const float* con_W2 = (const float*)d_in[16];
    const float* con_b2 = (const float*)d_in[17];

    float* out = (float*)d_out;
    float* out_logits = out;
    float* out_h      = out + NN * CC;
    float* out_c      = out + NN * CC + NN * HH;

    static int attr_done = 0;
    if (!attr_done) {
        cudaFuncSetAttribute(k_enc_hh,   cudaFuncAttributeMaxDynamicSharedMemorySize, 31744 * 4);
        cudaFuncSetAttribute(k_comb_hh,  cudaFuncAttributeMaxDynamicSharedMemorySize, 37888 * 4);
        cudaFuncSetAttribute(k_comb_head,cudaFuncAttributeMaxDynamicSharedMemorySize, 20480 * 4);
        attr_done = 1;
    }

    k_build<<<NN / 8, 256>>>(adj);
    k_enc_hh<<<GB, 256, 31744 * 4>>>(x, enc_W, enc_b, attn_W, attn_Wb, attn_a);

    int ping = 0;
    for (int l = 0; l < LL; l++) {
        k_sred<<<HH, HH>>>();
        k_sparse<<<NN, HH>>>(ping, attn_ab + l * NHD);
        if (l < LL - 1) {
            k_comb_hh<<<GB, 256, 37888 * 4>>>(ping, gcn_W + l * HH * HH, gcn_b + l * HH,
                                              attn_W + (l + 1) * NHD * HH * HD,
                                              attn_Wb + (l + 1) * NHD * HD,
                                              attn_a + (l + 1) * NHD * 2 * HD);
            ping ^= 1;
        } else {
            k_comb_head<<<GB, 256, 20480 * 4>>>(ping, gcn_W + l * HH * HH, gcn_b + l * HH,
                                                cls_W1, cls_b1, cls_W2, cls_b2,
                                                out_logits, out_h);
        }
    }
    k_cont<<<1, HH>>>(con_W1, con_b1, con_W2, con_b2, out_c);
}

// round 10
// speedup vs baseline: 1.5795x; 1.0180x over previous
#include <cuda_runtime.h>
#include <math.h>

#define NN 4096
#define FF 64
#define HH 128
#define NHD 4
#define HD 32
#define LL 3
#define CC 7
#define MAXD 96
#define GB 128      // 32-row GEMM blocks

// ---------------- device scratch ----------------
__device__ __align__(16) float g_h[2][NN * HH];
__device__ __align__(16) float g_hh[NN * HH];
__device__ __align__(16) float g_sup[NN * HH];
__device__ __align__(16) float g_att[NN * HH];
__device__ __align__(16) float g_ssrc[NN * NHD];
__device__ __align__(16) float g_sdst[NN * NHD];
__device__ __align__(16) float g_Spart[GB * HH];   // [blk][col]
__device__ __align__(16) float g_S[HH];
__device__ __align__(16) int   g_cols[NN * MAXD];
__device__ int   g_cnt[NN];
__device__ float g_dinv[NN];
__device__ __align__(16) float g_mpart[GB * HH];

// ---- register-tiled full-K GEMM: sW [k][col] (KD x 128), sB rows k-contiguous ----
template <int KD, int RS>
__device__ __forceinline__ void mm_full(const float* sW, const float* sB,
                                        float acc[4][4], int rt, int lane) {
#pragma unroll 4
    for (int k = 0; k < KD; k += 4) {
        float4 A0 = ((const float4*)sW)[(k + 0) * 32 + lane];
        float4 A1 = ((const float4*)sW)[(k + 1) * 32 + lane];
        float4 A2 = ((const float4*)sW)[(k + 2) * 32 + lane];
        float4 A3 = ((const float4*)sW)[(k + 3) * 32 + lane];
#pragma unroll
        for (int i = 0; i < 4; i++) {
            float4 bv = *(const float4*)(sB + (rt * 4 + i) * RS + k);
            acc[i][0] = fmaf(bv.x, A0.x, acc[i][0]);
            acc[i][1] = fmaf(bv.x, A0.y, acc[i][1]);
            acc[i][2] = fmaf(bv.x, A0.z, acc[i][2]);
            acc[i][3] = fmaf(bv.x, A0.w, acc[i][3]);
            acc[i][0] = fmaf(bv.y, A1.x, acc[i][0]);
            acc[i][1] = fmaf(bv.y, A1.y, acc[i][1]);
            acc[i][2] = fmaf(bv.y, A1.z, acc[i][2]);
            acc[i][3] = fmaf(bv.y, A1.w, acc[i][3]);
            acc[i][0] = fmaf(bv.z, A2.x, acc[i][0]);
            acc[i][1] = fmaf(bv.z, A2.y, acc[i][1]);
            acc[i][2] = fmaf(bv.z, A2.z, acc[i][2]);
            acc[i][3] = fmaf(bv.z, A2.w, acc[i][3]);
            acc[i][0] = fmaf(bv.w, A3.x, acc[i][0]);
            acc[i][1] = fmaf(bv.w, A3.y, acc[i][1]);
            acc[i][2] = fmaf(bv.w, A3.z, acc[i][2]);
            acc[i][3] = fmaf(bv.w, A3.w, acc[i][3]);
        }
    }
}

// ---- load attn_W[head][k][d] into sW2[k][col=head*32+d] (4096 float4) ----
__device__ __forceinline__ void load_attnW(float* sW2, const float* __restrict__ aW,
                                           int tid) {
    for (int i4 = tid; i4 < 4096; i4 += 256) {
        int k = i4 >> 5, colq = i4 & 31;
        ((float4*)sW2)[i4] = *(const float4*)(aW + (colq >> 3) * (HH * HD)
                                              + k * HD + ((colq & 7) << 2));
    }
}

// ---- hh epilogue+GEMM: hh = sB @ sW2 + Wb; ssrc/sdst/Spart ----
__device__ __forceinline__ void hh_phase(const float* sW2, const float* sB, float* sP,
                                         int r0, int blk,
                                         const float* __restrict__ Wb,
                                         const float* __restrict__ al) {
    int tid = threadIdx.x, lane = tid & 31, rt = tid >> 5;
    float acc[4][4];
#pragma unroll
    for (int i = 0; i < 4; i++)
#pragma unroll
        for (int j = 0; j < 4; j++) acc[i][j] = 0.0f;
    mm_full<HH, HH>(sW2, sB, acc, rt, lane);
    int col0 = lane * 4;
    int head = col0 >> 5;
    float4 wb = *(const float4*)(Wb + col0);
    float4 as = *(const float4*)(al + head * 64 + (col0 & 31));
    float4 ad = *(const float4*)(al + head * 64 + 32 + (col0 & 31));
    float cs0 = 0.f, cs1 = 0.f, cs2 = 0.f, cs3 = 0.f;
#pragma unroll
    for (int i = 0; i < 4; i++) {
        int r = r0 + rt * 4 + i;
        float v0 = acc[i][0] + wb.x, v1 = acc[i][1] + wb.y;
        float v2 = acc[i][2] + wb.z, v3 = acc[i][3] + wb.w;
        *(float4*)(g_hh + r * HH + col0) = make_float4(v0, v1, v2, v3);
        cs0 += v0; cs1 += v1; cs2 += v2; cs3 += v3;
        float vs = v0 * as.x + v1 * as.y + v2 * as.z + v3 * as.w;
        float vd = v0 * ad.x + v1 * ad.y + v2 * ad.z + v3 * ad.w;
        vs += __shfl_xor_sync(0xffffffffu, vs, 1);
        vs += __shfl_xor_sync(0xffffffffu, vs, 2);
        vs += __shfl_xor_sync(0xffffffffu, vs, 4);
        vd += __shfl_xor_sync(0xffffffffu, vd, 1);
        vd += __shfl_xor_sync(0xffffffffu, vd, 2);
        vd += __shfl_xor_sync(0xffffffffu, vd, 4);
        if ((lane & 7) == 0) {
            g_ssrc[r * NHD + head] = vs;
            g_sdst[r * NHD + head] = vd;
        }
    }
    *(float4*)(sP + rt * HH + col0) = make_float4(cs0, cs1, cs2, cs3);
    __syncthreads();
    if (tid < HH) {
        float s = 0.0f;
#pragma unroll
        for (int w = 0; w < 8; w++) s += sP[w * HH + tid];
        g_Spart[blk * HH + tid] = s;
    }
}

// ---------------- 1) edge-list build ----------------
__global__ void k_build(const float* __restrict__ adj) {
    int warp = (blockIdx.x * blockDim.x + threadIdx.x) >> 5;
    int lane = threadIdx.x & 31;
    const float4* row = (const float4*)(adj + (size_t)warp * NN);
    int base = warp * MAXD;
    int cnt = 0;
    for (int c0 = 0; c0 < NN / 4; c0 += 32) {
        float4 v = row[c0 + lane];
        float vals[4] = {v.x, v.y, v.z, v.w};
#pragma unroll
        for (int k = 0; k < 4; k++) {
            unsigned m = __ballot_sync(0xffffffffu, vals[k] > 0.0f);
            if (vals[k] > 0.0f) {
                int pos = cnt + __popc(m & ((1u << lane) - 1u));
                if (pos < MAXD) g_cols[base + pos] = (c0 + lane) * 4 + k;
            }
            cnt += __popc(m);
        }
    }
    if (lane == 0) {
        if (cnt > MAXD) cnt = MAXD;
        g_cnt[warp] = cnt;
        g_dinv[warp] = rsqrtf((float)cnt + 1.0f);
    }
}

// ---------------- 2) fused encoder GEMM + hh(layer0), full-W smem ----------------
__global__ void k_enc_hh(const float* __restrict__ x,
                         const float* __restrict__ W,
                         const float* __restrict__ b,
                         const float* __restrict__ aW0,
                         const float* __restrict__ aWb0,
                         const float* __restrict__ aa0) {
    extern __shared__ float sm[];
    float* sWe = sm;
    float* sW2 = sm + 8192;
    float* xs  = sm + 24576;
    float* sB  = sm + 26624;
    float* sP  = sm + 30720;
    int tid = threadIdx.x, lane = tid & 31, rt = tid >> 5;
    int blk = blockIdx.x, r0 = blk * 32;
    for (int i4 = tid; i4 < 2048; i4 += 256)
        ((float4*)sWe)[i4] = ((const float4*)W)[i4];
    load_attnW(sW2, aW0, tid);
    for (int i4 = tid; i4 < 512; i4 += 256)
        ((float4*)xs)[i4] = ((const float4*)(x + r0 * FF))[i4];
    __syncthreads();
    float acc[4][4];
#pragma unroll
    for (int i = 0; i < 4; i++)
#pragma unroll
        for (int j = 0; j < 4; j++) acc[i][j] = 0.0f;
    mm_full<FF, FF>(sWe, xs, acc, rt, lane);
    int col0 = lane * 4;
    float4 bb = *(const float4*)(b + col0);
#pragma unroll
    for (int i = 0; i < 4; i++) {
        int r = r0 + rt * 4 + i;
        float4 v = make_float4(fmaxf(acc[i][0] + bb.x, 0.0f),
                               fmaxf(acc[i][1] + bb.y, 0.0f),
                               fmaxf(acc[i][2] + bb.z, 0.0f),
                               fmaxf(acc[i][3] + bb.w, 0.0f));
        *(float4*)(sB + (rt * 4 + i) * HH + col0) = v;
        *(float4*)(g_h[0] + r * HH + col0) = v;
    }
    __syncthreads();
    hh_phase(sW2, sB, sP, r0, blk, aWb0, aa0);
}

// ---------------- 3) S reduce ----------------
__global__ void k_sred() {
    __shared__ float sm[4];
    int c = blockIdx.x, t = threadIdx.x;
    float s = g_Spart[t * HH + c];
#pragma unroll
    for (int off = 16; off; off >>= 1) s += __shfl_xor_sync(0xffffffffu, s, off);
    if ((t & 31) == 0) sm[t >> 5] = s;
    __syncthreads();
    if (t == 0) g_S[c] = sm[0] + sm[1] + sm[2] + sm[3];
}

// ---------------- 4) sparse: 4 nodes/block, 64 threads/node, float2 channels ----
__global__ void __launch_bounds__(256, 8)
k_sparse(int ping, const float* __restrict__ abl) {
    int tid = threadIdx.x;
    int w = tid >> 6;        // node slot 0..3
    int t = tid & 63;        // thread within node
    int n = blockIdx.x * 4 + w;
    int c0 = t * 2;          // channel pair
    int head = c0 >> 5;
    __shared__ int   cols_s[4][MAXD];
    __shared__ float dinv_s[4][MAXD];
    __shared__ float w_s[4][MAXD * NHD];
    __shared__ float ss[4][NHD];
    const float* hin = g_h[ping];
    int E = g_cnt[n];
    if (t < NHD) ss[w][t] = g_ssrc[n * NHD + t] + abl[t];
    for (int e = t; e < E; e += 64) {
        int j = g_cols[n * MAXD + e];
        cols_s[w][e] = j;
        dinv_s[w][e] = g_dinv[j];
    }
    __syncthreads();
    for (int idx = t; idx < E * NHD; idx += 64) {
        int e = idx >> 2, h2 = idx & 3;
        w_s[w][idx] = expf(ss[w][h2] + g_sdst[cols_s[w][e] * NHD + h2]) - 1.0f;
    }
    __syncthreads();
    float di = g_dinv[n];
    float2 hv = *(const float2*)(hin + n * HH + c0);
    float2 accg = make_float2(di * hv.x, di * hv.y);
    float2 acca = *(const float2*)(g_S + c0);
    float denom = (float)NN;
    const int* cl = cols_s[w];
    const float* dv = dinv_s[w];
    const float* wv = w_s[w];
    int e = 0;
    for (; e + 4 <= E; e += 4) {
        int j0 = cl[e], j1 = cl[e + 1], j2 = cl[e + 2], j3 = cl[e + 3];
        float2 h0 = *(const float2*)(hin + j0 * HH + c0);
        float2 h1 = *(const float2*)(hin + j1 * HH + c0);
        float2 h2 = *(const float2*)(hin + j2 * HH + c0);
        float2 h3 = *(const float2*)(hin + j3 * HH + c0);
        float2 q0 = *(const float2*)(g_hh + j0 * HH + c0);
        float2 q1 = *(const float2*)(g_hh + j1 * HH + c0);
        float2 q2 = *(const float2*)(g_hh + j2 * HH + c0);
        float2 q3 = *(const float2*)(g_hh + j3 * HH + c0);
        float d0 = dv[e], d1 = dv[e + 1], d2 = dv[e + 2], d3 = dv[e + 3];
        float w0 = wv[e * 4 + head], w1 = wv[(e + 1) * 4 + head];
        float w2 = wv[(e + 2) * 4 + head], w3 = wv[(e + 3) * 4 + head];
        accg.x += d0 * h0.x; accg.y += d0 * h0.y;
        accg.x += d1 * h1.x; accg.y += d1 * h1.y;
        accg.x += d2 * h2.x; accg.y += d2 * h2.y;
        accg.x += d3 * h3.x; accg.y += d3 * h3.y;
        acca.x += w0 * q0.x; acca.y += w0 * q0.y;
        acca.x += w1 * q1.x; acca.y += w1 * q1.y;
        acca.x += w2 * q2.x; acca.y += w2 * q2.y;
        acca.x += w3 * q3.x; acca.y += w3 * q3.y;
        denom += w0 + w1 + w2 + w3;
    }
    for (; e < E; e++) {
        int j = cl[e];
        float2 hj = *(const float2*)(hin + j * HH + c0);
        float2 qj = *(const float2*)(g_hh + j * HH + c0);
        float dj = dv[e];
        float ww = wv[e * 4 + head];
        accg.x += dj * hj.x; accg.y += dj * hj.y;
        acca.x += ww * qj.x; acca.y += ww * qj.y;
        denom += ww;
    }
    float inv = 1.0f / denom;
    *(float2*)(g_sup + n * HH + c0) = make_float2(di * accg.x, di * accg.y);
    *(float2*)(g_att + n * HH + c0) = make_float2(acca.x * inv, acca.y * inv);
}

// ---------------- 5) fused combine GEMM + next-layer hh GEMM (full-W smem) -------
__global__ void k_comb_hh(int ping, const float* __restrict__ Wl,
                          const float* __restrict__ bl,
                          const float* __restrict__ aWn,
                          const float* __restrict__ aWbn,
                          const float* __restrict__ aan) {
    extern __shared__ float sm[];
    float* sW1 = sm;
    float* sW2 = sm + 16384;
    float* sB  = sm + 32768;
    float* sP  = sm + 36864;
    float* hout = g_h[ping ^ 1];
    int tid = threadIdx.x, lane = tid & 31, rt = tid >> 5;
    int blk = blockIdx.x, r0 = blk * 32;
    for (int i4 = tid; i4 < 4096; i4 += 256)
        ((float4*)sW1)[i4] = ((const float4*)Wl)[i4];
    load_attnW(sW2, aWn, tid);
    for (int i4 = tid; i4 < 1024; i4 += 256)
        ((float4*)sB)[i4] = ((const float4*)(g_sup + r0 * HH))[i4];
    __syncthreads();
    float acc[4][4];
#pragma unroll
    for (int i = 0; i < 4; i++)
#pragma unroll
        for (int j = 0; j < 4; j++) acc[i][j] = 0.0f;
    mm_full<HH, HH>(sW1, sB, acc, rt, lane);
    int col0 = lane * 4;
    float4 bb = *(const float4*)(bl + col0);
    __syncthreads();
#pragma unroll
    for (int i = 0; i < 4; i++) {
        int r = r0 + rt * 4 + i;
        float4 at = *(const float4*)(g_att + r * HH + col0);
        float4 v;
        v.x = fmaxf(fmaxf(acc[i][0] + bb.x, 0.0f) + at.x, 0.0f);
        v.y = fmaxf(fmaxf(acc[i][1] + bb.y, 0.0f) + at.y, 0.0f);
        v.z = fmaxf(fmaxf(acc[i][2] + bb.z, 0.0f) + at.z, 0.0f);
        v.w = fmaxf(fmaxf(acc[i][3] + bb.w, 0.0f) + at.w, 0.0f);
        *(float4*)(sB + (rt * 4 + i) * HH + col0) = v;
        *(float4*)(hout + r * HH + col0) = v;
    }
    __syncthreads();
    hh_phase(sW2, sB, sP, r0, blk, aWbn, aan);
}

// ---------------- 6) fused final combine + classifier head + mean partials -------
__global__ void k_comb_head(int ping, const float* __restrict__ Wl,
                            const float* __restrict__ bl,
                            const float* __restrict__ W1, const float* __restrict__ b1,
                            const float* __restrict__ W2, const float* __restrict__ b2,
                            float* __restrict__ out_logits, float* __restrict__ out_h) {
    extern __shared__ float sm[];
    float* sW1 = sm;
    float* sB  = sm + 16384;
    int tid = threadIdx.x, lane = tid & 31, rt = tid >> 5;
    int blk = blockIdx.x, r0 = blk * 32;
    for (int i4 = tid; i4 < 4096; i4 += 256)
        ((float4*)sW1)[i4] = ((const float4*)Wl)[i4];
    for (int i4 = tid; i4 < 1024; i4 += 256)
        ((float4*)sB)[i4] = ((const float4*)(g_sup + r0 * HH))[i4];
    __syncthreads();
    float acc[4][4];
#pragma unroll
    for (int i = 0; i < 4; i++)
#pragma unroll
        for (int j = 0; j < 4; j++) acc[i][j] = 0.0f;
    mm_full<HH, HH>(sW1, sB, acc, rt, lane);
    int col0 = lane * 4;
    float4 bb = *(const float4*)(bl + col0);
    __syncthreads();
#pragma unroll
    for (int i = 0; i < 4; i++) {
        int r = r0 + rt * 4 + i;
        float4 at = *(const float4*)(g_att + r * HH + col0);
        float4 v;
        v.x = fmaxf(fmaxf(acc[i][0] + bb.x, 0.0f) + at.x, 0.0f);
        v.y = fmaxf(fmaxf(acc[i][1] + bb.y, 0.0f) + at.y, 0.0f);
        v.z = fmaxf(fmaxf(acc[i][2] + bb.z, 0.0f) + at.z, 0.0f);
        v.w = fmaxf(fmaxf(acc[i][3] + bb.w, 0.0f) + at.w, 0.0f);
        *(float4*)(sB + (rt * 4 + i) * HH + col0) = v;
        *(float4*)(out_h + r * HH + col0) = v;
    }
    __syncthreads();
    if (tid < HH) {
        float s = 0.0f;
#pragma unroll 8
        for (int r = 0; r < 32; r++) s += sB[r * HH + tid];
        g_mpart[blk * HH + tid] = s;
    }
    {
        int c6 = tid & 63, rg = tid >> 6;
        float a8[8];
#pragma unroll
        for (int i = 0; i < 8; i++) a8[i] = b1[c6];
        for (int k = 0; k < HH; k++) {
            float wvv = W1[k * 64 + c6];
#pragma unroll
            for (int i = 0; i < 8; i++)
                a8[i] += sB[(rg * 8 + i) * HH + k] * wvv;
        }
        __syncthreads();
#pragma unroll
        for (int i = 0; i < 8; i++)
            sW1[(rg * 8 + i) * 64 + c6] = fmaxf(a8[i], 0.0f);
    }
    __syncthreads();
    if (tid < 32 * CC) {
        int r = tid / CC, q = tid - r * CC;
        float a = b2[q];
#pragma unroll 16
        for (int k = 0; k < 64; k++) a += sW1[r * 64 + k] * W2[k * CC + q];
        out_logits[(r0 + r) * CC + q] = a;
    }
}

// ---------------- 7) contagion head ----------------
__global__ void k_cont(const float* __restrict__ W1, const float* __restrict__ b1,
                       const float* __restrict__ W2, const float* __restrict__ b2,
                       float* __restrict__ out_c) {
    __shared__ float ms[HH];
    __shared__ float t1[64];
    int c = threadIdx.x;
    float s = 0.0f;
    for (int b = 0; b < GB; b++) s += g_mpart[b * HH + c];
    ms[c] = s * (1.0f / (float)NN);
    __syncthreads();
    if (c < 64) {
        float a = b1[c];
#pragma unroll 16
        for (int k = 0; k < HH; k++) a += ms[k] * W1[k * 64 + c];
        t1[c] = fmaxf(a, 0.0f);
    }
    __syncthreads();
    if (c == 0) {
        float a = b2[0];
        for (int k = 0; k < 64; k++) a += t1[k] * W2[k];
        out_c[0] = a;
    }
}

extern "C" void kernel_launch(void* const* d_in, const int* in_sizes, int n_in,
                              void* d_out, int out_size) {
    const float* x      = (const float*)d_in[0];
    const float* adj    = (const float*)d_in[1];
    const float* enc_W  = (const float*)d_in[2];
    const float* enc_b  = (const float*)d_in[3];
    const float* gcn_W  = (const float*)d_in[4];
    const float* gcn_b  = (const float*)d_in[5];
    const float* attn_W = (const float*)d_in[6];
    const float* attn_Wb= (const float*)d_in[7];
    const float* attn_a = (const float*)d_in[8];
    const float* attn_ab= (const float*)d_in[9];
    const float* cls_W1 = (const float*)d_in[10];
    const float* cls_b1 = (const float*)d_in[11];
    const float* cls_W2 = (const float*)d_in[12];
    const float* cls_b2 = (const float*)d_in[13];
    const float* con_W1 = (const float*)d_in[14];
    const float* con_b1 = (const float*)d_in[15];
    const float* con_W2 = (const float*)d_in[16];
    const float* con_b2 = (const float*)d_in[17];

    float* out = (float*)d_out;
    float* out_logits = out;
    float* out_h      = out + NN * CC;
    float* out_c      = out + NN * CC + NN * HH;

    static int attr_done = 0;
    if (!attr_done) {
        cudaFuncSetAttribute(k_enc_hh,   cudaFuncAttributeMaxDynamicSharedMemorySize, 31744 * 4);
        cudaFuncSetAttribute(k_comb_hh,  cudaFuncAttributeMaxDynamicSharedMemorySize, 37888 * 4);
        cudaFuncSetAttribute(k_comb_head,cudaFuncAttributeMaxDynamicSharedMemorySize, 20480 * 4);
        attr_done = 1;
    }

    k_build<<<NN / 8, 256>>>(adj);
    k_enc_hh<<<GB, 256, 31744 * 4>>>(x, enc_W, enc_b, attn_W, attn_Wb, attn_a);

    int ping = 0;
    for (int l = 0; l < LL; l++) {
        k_sred<<<HH, HH>>>();
        k_sparse<<<NN / 4, 256>>>(ping, attn_ab + l * NHD);
        if (l < LL - 1) {
            k_comb_hh<<<GB, 256, 37888 * 4>>>(ping, gcn_W + l * HH * HH, gcn_b + l * HH,
                                              attn_W + (l + 1) * NHD * HH * HD,
                                              attn_Wb + (l + 1) * NHD * HD,
                                              attn_a + (l + 1) * NHD * 2 * HD);
            ping ^= 1;
        } else {
            k_comb_head<<<GB, 256, 20480 * 4>>>(ping, gcn_W + l * HH * HH, gcn_b + l * HH,
                                                cls_W1, cls_b1, cls_W2, cls_b2,
                                                out_logits, out_h);
        }
    }
    k_cont<<<1, HH>>>(con_W1, con_b1, con_W2, con_b2, out_c);
}

// round 12
// speedup vs baseline: 1.6362x; 1.0359x over previous
#include <cuda_runtime.h>
#include <math.h>

#define NN 4096
#define FF 64
#define HH 128
#define NHD 4
#define HD 32
#define LL 3
#define CC 7
#define MAXD 96
#define GB 128      // 32-row GEMM blocks

// ---------------- device scratch ----------------
// packed per node: [pair p: h[2p], h[2p+1], hh[2p], hh[2p+1]]  (256 floats/node)
__device__ __align__(16) float g_pack[NN * 256];
__device__ __align__(16) float g_sup[NN * HH];
__device__ __align__(16) float g_att[NN * HH];
__device__ __align__(16) float g_ssrc[NN * NHD];
__device__ __align__(16) float g_sdst[NN * NHD];
__device__ __align__(16) float g_Spart[GB * HH];   // [blk][col]
__device__ __align__(16) float g_S[HH];
__device__ __align__(16) int   g_cols[NN * MAXD];
__device__ int   g_cnt[NN];
__device__ float g_dinv[NN];
__device__ __align__(16) float g_mpart[GB * HH];

// ---- register-tiled full-K GEMM: sW [k][col] (KD x 128), sB rows k-contiguous ----
template <int KD, int RS>
__device__ __forceinline__ void mm_full(const float* sW, const float* sB,
                                        float acc[4][4], int rt, int lane) {
#pragma unroll 4
    for (int k = 0; k < KD; k += 4) {
        float4 A0 = ((const float4*)sW)[(k + 0) * 32 + lane];
        float4 A1 = ((const float4*)sW)[(k + 1) * 32 + lane];
        float4 A2 = ((const float4*)sW)[(k + 2) * 32 + lane];
        float4 A3 = ((const float4*)sW)[(k + 3) * 32 + lane];
#pragma unroll
        for (int i = 0; i < 4; i++) {
            float4 bv = *(const float4*)(sB + (rt * 4 + i) * RS + k);
            acc[i][0] = fmaf(bv.x, A0.x, acc[i][0]);
            acc[i][1] = fmaf(bv.x, A0.y, acc[i][1]);
            acc[i][2] = fmaf(bv.x, A0.z, acc[i][2]);
            acc[i][3] = fmaf(bv.x, A0.w, acc[i][3]);
            acc[i][0] = fmaf(bv.y, A1.x, acc[i][0]);
            acc[i][1] = fmaf(bv.y, A1.y, acc[i][1]);
            acc[i][2] = fmaf(bv.y, A1.z, acc[i][2]);
            acc[i][3] = fmaf(bv.y, A1.w, acc[i][3]);
            acc[i][0] = fmaf(bv.z, A2.x, acc[i][0]);
            acc[i][1] = fmaf(bv.z, A2.y, acc[i][1]);
            acc[i][2] = fmaf(bv.z, A2.z, acc[i][2]);
            acc[i][3] = fmaf(bv.z, A2.w, acc[i][3]);
            acc[i][0] = fmaf(bv.w, A3.x, acc[i][0]);
            acc[i][1] = fmaf(bv.w, A3.y, acc[i][1]);
            acc[i][2] = fmaf(bv.w, A3.z, acc[i][2]);
            acc[i][3] = fmaf(bv.w, A3.w, acc[i][3]);
        }
    }
}

// ---- load attn_W[head][k][d] into sW2[k][col=head*32+d] (4096 float4) ----
__device__ __forceinline__ void load_attnW(float* sW2, const float* __restrict__ aW,
                                           int tid) {
    for (int i4 = tid; i4 < 4096; i4 += 256) {
        int k = i4 >> 5, colq = i4 & 31;
        ((float4*)sW2)[i4] = *(const float4*)(aW + (colq >> 3) * (HH * HD)
                                              + k * HD + ((colq & 7) << 2));
    }
}

// ---- hh epilogue+GEMM: hh = sB @ sW2 + Wb -> g_pack hh slots; ssrc/sdst/Spart ----
__device__ __forceinline__ void hh_phase(const float* sW2, const float* sB, float* sP,
                                         int r0, int blk,
                                         const float* __restrict__ Wb,
                                         const float* __restrict__ al) {
    int tid = threadIdx.x, lane = tid & 31, rt = tid >> 5;
    float acc[4][4];
#pragma unroll
    for (int i = 0; i < 4; i++)
#pragma unroll
        for (int j = 0; j < 4; j++) acc[i][j] = 0.0f;
    mm_full<HH, HH>(sW2, sB, acc, rt, lane);
    int col0 = lane * 4;
    int head = col0 >> 5;
    float4 wb = *(const float4*)(Wb + col0);
    float4 as = *(const float4*)(al + head * 64 + (col0 & 31));
    float4 ad = *(const float4*)(al + head * 64 + 32 + (col0 & 31));
    float cs0 = 0.f, cs1 = 0.f, cs2 = 0.f, cs3 = 0.f;
#pragma unroll
    for (int i = 0; i < 4; i++) {
        int r = r0 + rt * 4 + i;
        float v0 = acc[i][0] + wb.x, v1 = acc[i][1] + wb.y;
        float v2 = acc[i][2] + wb.z, v3 = acc[i][3] + wb.w;
        int base = r * 256 + col0 * 2;
        *(float2*)(g_pack + base + 2) = make_float2(v0, v1);
        *(float2*)(g_pack + base + 6) = make_float2(v2, v3);
        cs0 += v0; cs1 += v1; cs2 += v2; cs3 += v3;
        float vs = v0 * as.x + v1 * as.y + v2 * as.z + v3 * as.w;
        float vd = v0 * ad.x + v1 * ad.y + v2 * ad.z + v3 * ad.w;
        vs += __shfl_xor_sync(0xffffffffu, vs, 1);
        vs += __shfl_xor_sync(0xffffffffu, vs, 2);
        vs += __shfl_xor_sync(0xffffffffu, vs, 4);
        vd += __shfl_xor_sync(0xffffffffu, vd, 1);
        vd += __shfl_xor_sync(0xffffffffu, vd, 2);
        vd += __shfl_xor_sync(0xffffffffu, vd, 4);
        if ((lane & 7) == 0) {
            g_ssrc[r * NHD + head] = vs;
            g_sdst[r * NHD + head] = vd;
        }
    }
    *(float4*)(sP + rt * HH + col0) = make_float4(cs0, cs1, cs2, cs3);
    __syncthreads();
    if (tid < HH) {
        float s = 0.0f;
#pragma unroll
        for (int w = 0; w < 8; w++) s += sP[w * HH + tid];
        g_Spart[blk * HH + tid] = s;
    }
}

// ---------------- 1) edge-list build ----------------
__global__ void k_build(const float* __restrict__ adj) {
    int warp = (blockIdx.x * blockDim.x + threadIdx.x) >> 5;
    int lane = threadIdx.x & 31;
    const float4* row = (const float4*)(adj + (size_t)warp * NN);
    int base = warp * MAXD;
    int cnt = 0;
    for (int c0 = 0; c0 < NN / 4; c0 += 32) {
        float4 v = row[c0 + lane];
        float vals[4] = {v.x, v.y, v.z, v.w};
#pragma unroll
        for (int k = 0; k < 4; k++) {
            unsigned m = __ballot_sync(0xffffffffu, vals[k] > 0.0f);
            if (vals[k] > 0.0f) {
                int pos = cnt + __popc(m & ((1u << lane) - 1u));
                if (pos < MAXD) g_cols[base + pos] = (c0 + lane) * 4 + k;
            }
            cnt += __popc(m);
        }
    }
    if (lane == 0) {
        if (cnt > MAXD) cnt = MAXD;
        g_cnt[warp] = cnt;
        g_dinv[warp] = rsqrtf((float)cnt + 1.0f);
    }
}

// ---------------- 2) fused encoder GEMM + hh(layer0), full-W smem ----------------
__global__ void k_enc_hh(const float* __restrict__ x,
                         const float* __restrict__ W,
                         const float* __restrict__ b,
                         const float* __restrict__ aW0,
                         const float* __restrict__ aWb0,
                         const float* __restrict__ aa0) {
    extern __shared__ float sm[];
    float* sWe = sm;
    float* sW2 = sm + 8192;
    float* xs  = sm + 24576;
    float* sB  = sm + 26624;
    float* sP  = sm + 30720;
    int tid = threadIdx.x, lane = tid & 31, rt = tid >> 5;
    int blk = blockIdx.x, r0 = blk * 32;
    for (int i4 = tid; i4 < 2048; i4 += 256)
        ((float4*)sWe)[i4] = ((const float4*)W)[i4];
    load_attnW(sW2, aW0, tid);
    for (int i4 = tid; i4 < 512; i4 += 256)
        ((float4*)xs)[i4] = ((const float4*)(x + r0 * FF))[i4];
    __syncthreads();
    float acc[4][4];
#pragma unroll
    for (int i = 0; i < 4; i++)
#pragma unroll
        for (int j = 0; j < 4; j++) acc[i][j] = 0.0f;
    mm_full<FF, FF>(sWe, xs, acc, rt, lane);
    int col0 = lane * 4;
    float4 bb = *(const float4*)(b + col0);
#pragma unroll
    for (int i = 0; i < 4; i++) {
        int r = r0 + rt * 4 + i;
        float4 v = make_float4(fmaxf(acc[i][0] + bb.x, 0.0f),
                               fmaxf(acc[i][1] + bb.y, 0.0f),
                               fmaxf(acc[i][2] + bb.z, 0.0f),
                               fmaxf(acc[i][3] + bb.w, 0.0f));
        *(float4*)(sB + (rt * 4 + i) * HH + col0) = v;
        int base = r * 256 + col0 * 2;
        *(float2*)(g_pack + base + 0) = make_float2(v.x, v.y);
        *(float2*)(g_pack + base + 4) = make_float2(v.z, v.w);
    }
    __syncthreads();
    hh_phase(sW2, sB, sP, r0, blk, aWb0, aa0);
}

// ---------------- 3) S reduce ----------------
__global__ void k_sred() {
    __shared__ float sm[4];
    int c = blockIdx.x, t = threadIdx.x;
    float s = g_Spart[t * HH + c];
#pragma unroll
    for (int off = 16; off; off >>= 1) s += __shfl_xor_sync(0xffffffffu, s, off);
    if ((t & 31) == 0) sm[t >> 5] = s;
    __syncthreads();
    if (t == 0) g_S[c] = sm[0] + sm[1] + sm[2] + sm[3];
}

// ---------------- 4) sparse: 4 nodes/block, 64 thr/node, packed float4 gather ----
__global__ void __launch_bounds__(256, 8)
k_sparse(const float* __restrict__ abl) {
    int tid = threadIdx.x;
    int w = tid >> 6;        // node slot 0..3
    int t = tid & 63;        // thread within node
    int n = blockIdx.x * 4 + w;
    int c0 = t * 2;          // channel pair
    int head = t >> 4;
    __shared__ int   cols_s[4][MAXD];   // stores j*64 (float4 base index)
    __shared__ float dinv_s[4][MAXD];
    __shared__ float w_s[4][MAXD * NHD];
    __shared__ float ss[4][NHD];
    const float4* pk = (const float4*)g_pack;
    int E = g_cnt[n];
    if (t < NHD) ss[w][t] = g_ssrc[n * NHD + t] + abl[t];
    for (int e = t; e < E; e += 64) {
        int j = g_cols[n * MAXD + e];
        cols_s[w][e] = j * 64;
        dinv_s[w][e] = g_dinv[j];
    }
    __syncthreads();
    for (int idx = t; idx < E * NHD; idx += 64) {
        int e = idx >> 2, h2 = idx & 3;
        w_s[w][idx] = expf(ss[w][h2] + g_sdst[(cols_s[w][e] >> 4) + h2]) - 1.0f;
    }
    __syncthreads();
    float di = g_dinv[n];
    float4 hv = pk[n * 64 + t];
    float2 accg = make_float2(di * hv.x, di * hv.y);
    float2 acca = *(const float2*)(g_S + c0);
    float denom = (float)NN;
    const int* cl = cols_s[w];
    const float* dv = dinv_s[w];
    const float* wv = w_s[w];
    int e = 0;
    for (; e + 4 <= E; e += 4) {
        float4 f0 = pk[cl[e] + t];
        float4 f1 = pk[cl[e + 1] + t];
        float4 f2 = pk[cl[e + 2] + t];
        float4 f3 = pk[cl[e + 3] + t];
        float d0 = dv[e], d1 = dv[e + 1], d2 = dv[e + 2], d3 = dv[e + 3];
        float w0 = wv[e * 4 + head], w1 = wv[(e + 1) * 4 + head];
        float w2 = wv[(e + 2) * 4 + head], w3 = wv[(e + 3) * 4 + head];
        accg.x += d0 * f0.x; accg.y += d0 * f0.y;
        accg.x += d1 * f1.x; accg.y += d1 * f1.y;
        accg.x += d2 * f2.x; accg.y += d2 * f2.y;
        accg.x += d3 * f3.x; accg.y += d3 * f3.y;
        acca.x += w0 * f0.z; acca.y += w0 * f0.w;
        acca.x += w1 * f1.z; acca.y += w1 * f1.w;
        acca.x += w2 * f2.z; acca.y += w2 * f2.w;
        acca.x += w3 * f3.z; acca.y += w3 * f3.w;
        denom += w0 + w1 + w2 + w3;
    }
    for (; e < E; e++) {
        float4 f = pk[cl[e] + t];
        float dj = dv[e];
        float ww = wv[e * 4 + head];
        accg.x += dj * f.x; accg.y += dj * f.y;
        acca.x += ww * f.z; acca.y += ww * f.w;
        denom += ww;
    }
    float inv = 1.0f / denom;
    *(float2*)(g_sup + n * HH + c0) = make_float2(di * accg.x, di * accg.y);
    *(float2*)(g_att + n * HH + c0) = make_float2(acca.x * inv, acca.y * inv);
}

// ---------------- 5) fused combine GEMM + next-layer hh GEMM (full-W smem) -------
__global__ void k_comb_hh(const float* __restrict__ Wl,
                          const float* __restrict__ bl,
                          const float* __restrict__ aWn,
                          const float* __restrict__ aWbn,
                          const float* __restrict__ aan) {
    extern __shared__ float sm[];
    float* sW1 = sm;
    float* sW2 = sm + 16384;
    float* sB  = sm + 32768;
    float* sP  = sm + 36864;
    int tid = threadIdx.x, lane = tid & 31, rt = tid >> 5;
    int blk = blockIdx.x, r0 = blk * 32;
    for (int i4 = tid; i4 < 4096; i4 += 256)
        ((float4*)sW1)[i4] = ((const float4*)Wl)[i4];
    load_attnW(sW2, aWn, tid);
    for (int i4 = tid; i4 < 1024; i4 += 256)
        ((float4*)sB)[i4] = ((const float4*)(g_sup + r0 * HH))[i4];
    __syncthreads();
    float acc[4][4];
#pragma unroll
    for (int i = 0; i < 4; i++)
#pragma unroll
        for (int j = 0; j < 4; j++) acc[i][j] = 0.0f;
    mm_full<HH, HH>(sW1, sB, acc, rt, lane);
    int col0 = lane * 4;
    float4 bb = *(const float4*)(bl + col0);
    __syncthreads();
#pragma unroll
    for (int i = 0; i < 4; i++) {
        int r = r0 + rt * 4 + i;
        float4 at = *(const float4*)(g_att + r * HH + col0);
        float4 v;
        v.x = fmaxf(fmaxf(acc[i][0] + bb.x, 0.0f) + at.x, 0.0f);
        v.y = fmaxf(fmaxf(acc[i][1] + bb.y, 0.0f) + at.y, 0.0f);
        v.z = fmaxf(fmaxf(acc[i][2] + bb.z, 0.0f) + at.z, 0.0f);
        v.w = fmaxf(fmaxf(acc[i][3] + bb.w, 0.0f) + at.w, 0.0f);
        *(float4*)(sB + (rt * 4 + i) * HH + col0) = v;
        int base = r * 256 + col0 * 2;
        *(float2*)(g_pack + base + 0) = make_float2(v.x, v.y);
        *(float2*)(g_pack + base + 4) = make_float2(v.z, v.w);
    }
    __syncthreads();
    hh_phase(sW2, sB, sP, r0, blk, aWbn, aan);
}

// ---------------- 6) fused final combine + classifier head + mean partials -------
__global__ void k_comb_head(const float* __restrict__ Wl,
                            const float* __restrict__ bl,
                            const float* __restrict__ W1, const float* __restrict__ b1,
                            const float* __restrict__ W2, const float* __restrict__ b2,
                            float* __restrict__ out_logits, float* __restrict__ out_h) {
    extern __shared__ float sm[];
    float* sW1 = sm;
    float* sB  = sm + 16384;
    int tid = threadIdx.x, lane = tid & 31, rt = tid >> 5;
    int blk = blockIdx.x, r0 = blk * 32;
    for (int i4 = tid; i4 < 4096; i4 += 256)
        ((float4*)sW1)[i4] = ((const float4*)Wl)[i4];
    for (int i4 = tid; i4 < 1024; i4 += 256)
        ((float4*)sB)[i4] = ((const float4*)(g_sup + r0 * HH))[i4];
    __syncthreads();
    float acc[4][4];
#pragma unroll
    for (int i = 0; i < 4; i++)
#pragma unroll
        for (int j = 0; j < 4; j++) acc[i][j] = 0.0f;
    mm_full<HH, HH>(sW1, sB, acc, rt, lane);
    int col0 = lane * 4;
    float4 bb = *(const float4*)(bl + col0);
    __syncthreads();
#pragma unroll
    for (int i = 0; i < 4; i++) {
        int r = r0 + rt * 4 + i;
        float4 at = *(const float4*)(g_att + r * HH + col0);
        float4 v;
        v.x = fmaxf(fmaxf(acc[i][0] + bb.x, 0.0f) + at.x, 0.0f);
        v.y = fmaxf(fmaxf(acc[i][1] + bb.y, 0.0f) + at.y, 0.0f);
        v.z = fmaxf(fmaxf(acc[i][2] + bb.z, 0.0f) + at.z, 0.0f);
        v.w = fmaxf(fmaxf(acc[i][3] + bb.w, 0.0f) + at.w, 0.0f);
        *(float4*)(sB + (rt * 4 + i) * HH + col0) = v;
        *(float4*)(out_h + r * HH + col0) = v;
    }
    __syncthreads();
    if (tid < HH) {
        float s = 0.0f;
#pragma unroll 8
        for (int r = 0; r < 32; r++) s += sB[r * HH + tid];
        g_mpart[blk * HH + tid] = s;
    }
    {
        int c6 = tid & 63, rg = tid >> 6;
        float a8[8];
#pragma unroll
        for (int i = 0; i < 8; i++) a8[i] = b1[c6];
        for (int k = 0; k < HH; k++) {
            float wvv = W1[k * 64 + c6];
#pragma unroll
            for (int i = 0; i < 8; i++)
                a8[i] += sB[(rg * 8 + i) * HH + k] * wvv;
        }
        __syncthreads();
#pragma unroll
        for (int i = 0; i < 8; i++)
            sW1[(rg * 8 + i) * 64 + c6] = fmaxf(a8[i], 0.0f);
    }
    __syncthreads();
    if (tid < 32 * CC) {
        int r = tid / CC, q = tid - r * CC;
        float a = b2[q];
#pragma unroll 16
        for (int k = 0; k < 64; k++) a += sW1[r * 64 + k] * W2[k * CC + q];
        out_logits[(r0 + r) * CC + q] = a;
    }
}

// ---------------- 7) contagion head ----------------
__global__ void k_cont(const float* __restrict__ W1, const float* __restrict__ b1,
                       const float* __restrict__ W2, const float* __restrict__ b2,
                       float* __restrict__ out_c) {
    __shared__ float ms[HH];
    __shared__ float t1[64];
    int c = threadIdx.x;
    float s = 0.0f;
    for (int b = 0; b < GB; b++) s += g_mpart[b * HH + c];
    ms[c] = s * (1.0f / (float)NN);
    __syncthreads();
    if (c < 64) {
        float a = b1[c];
#pragma unroll 16
        for (int k = 0; k < HH; k++) a += ms[k] * W1[k * 64 + c];
        t1[c] = fmaxf(a, 0.0f);
    }
    __syncthreads();
    if (c == 0) {
        float a = b2[0];
        for (int k = 0; k < 64; k++) a += t1[k] * W2[k];
        out_c[0] = a;
    }
}

extern "C" void kernel_launch(void* const* d_in, const int* in_sizes, int n_in,
                              void* d_out, int out_size) {
    const float* x      = (const float*)d_in[0];
    const float* adj    = (const float*)d_in[1];
    const float* enc_W  = (const float*)d_in[2];
    const float* enc_b  = (const float*)d_in[3];
    const float* gcn_W  = (const float*)d_in[4];
    const float* gcn_b  = (const float*)d_in[5];
    const float* attn_W = (const float*)d_in[6];
    const float* attn_Wb= (const float*)d_in[7];
    const float* attn_a = (const float*)d_in[8];
    const float* attn_ab= (const float*)d_in[9];
    const float* cls_W1 = (const float*)d_in[10];
    const float* cls_b1 = (const float*)d_in[11];
    const float* cls_W2 = (const float*)d_in[12];
    const float* cls_b2 = (const float*)d_in[13];
    const float* con_W1 = (const float*)d_in[14];
    const float* con_b1 = (const float*)d_in[15];
    const float* con_W2 = (const float*)d_in[16];
    const float* con_b2 = (const float*)d_in[17];

    float* out = (float*)d_out;
    float* out_logits = out;
    float* out_h      = out + NN * CC;
    float* out_c      = out + NN * CC + NN * HH;

    static int attr_done = 0;
    if (!attr_done) {
        cudaFuncSetAttribute(k_enc_hh,   cudaFuncAttributeMaxDynamicSharedMemorySize, 31744 * 4);
        cudaFuncSetAttribute(k_comb_hh,  cudaFuncAttributeMaxDynamicSharedMemorySize, 37888 * 4);
        cudaFuncSetAttribute(k_comb_head,cudaFuncAttributeMaxDynamicSharedMemorySize, 20480 * 4);
        attr_done = 1;
    }

    k_build<<<NN / 8, 256>>>(adj);
    k_enc_hh<<<GB, 256, 31744 * 4>>>(x, enc_W, enc_b, attn_W, attn_Wb, attn_a);

    for (int l = 0; l < LL; l++) {
        k_sred<<<HH, HH>>>();
        k_sparse<<<NN / 4, 256>>>(attn_ab + l * NHD);
        if (l < LL - 1) {
            k_comb_hh<<<GB, 256, 37888 * 4>>>(gcn_W + l * HH * HH, gcn_b + l * HH,
                                              attn_W + (l + 1) * NHD * HH * HD,
                                              attn_Wb + (l + 1) * NHD * HD,
                                              attn_a + (l + 1) * NHD * 2 * HD);
        } else {
            k_comb_head<<<GB, 256, 20480 * 4>>>(gcn_W + l * HH * HH, gcn_b + l * HH,
                                                cls_W1, cls_b1, cls_W2, cls_b2,
                                                out_logits, out_h);
        }
    }
    k_cont<<<1, HH>>>(con_W1, con_b1, con_W2, con_b2, out_c);
}